// round 2
// baseline (speedup 1.0000x reference)
#include <cuda_runtime.h>
#include <cstdint>
#include <cstddef>

#define BB 32
#define TT 128
#define LL 64
#define HH 512
#define AA 256
#define DD 512
#define NCOL 2048

// ---------------- device scratch (no cudaMalloc allowed) ----------------
__device__ float g_xg[(size_t)TT * BB * NCOL];   // [t][b][gate*512+ch] = X@W + b
__device__ float g_ctr[(size_t)BB * LL * AA];    // ctx_trans = context@W1c + b1
__device__ float g_gbuf[(size_t)BB * NCOL];      // per-step partial gate sums
__device__ float g_hbuf[(size_t)BB * HH];        // h(t) state
__device__ unsigned int g_bar_count = 0;
__device__ unsigned int g_bar_gen = 0;

// ---------------- grid barrier (sense-reversing, replay-safe) ----------------
__device__ __forceinline__ void grid_barrier(unsigned int nb) {
    __syncthreads();
    if (threadIdx.x == 0) {
        __threadfence();
        volatile unsigned int* vgen = &g_bar_gen;
        unsigned int gen = *vgen;
        unsigned int old = atomicAdd(&g_bar_count, 1u);
        if (old == nb - 1u) {
            g_bar_count = 0u;       // safe: others blocked until gen bumps
            __threadfence();
            atomicAdd(&g_bar_gen, 1u);
        } else {
            while (*vgen == gen) { }
            __threadfence();
        }
    }
    __syncthreads();
}

// ---------------- generic projection GEMM: Out[M,Ncols] = A[M,512] @ W + bias ----
// tb_mode: row r -> X[(b*T + t)] with r = t*32+b (so output is t-major for the scan)
__global__ void __launch_bounds__(256) gemm_proj(
    const float* __restrict__ A,
    const float* __restrict__ Wa, const float* __restrict__ Wb,
    const float* __restrict__ Wc, const float* __restrict__ Wd,
    const float* __restrict__ ba, const float* __restrict__ bbi,
    const float* __restrict__ bc, const float* __restrict__ bd,
    float* __restrict__ Out, int Ncols, int wN, int wstride, int tb_mode)
{
    __shared__ float As[16][64];
    __shared__ float Bs[16][64];
    int tid = threadIdx.x;
    int ntile = blockIdx.x, mtile = blockIdx.y;

    int gate = (ntile * 64) / 512;
    const float* Wsel = (gate == 0) ? Wa : (gate == 1) ? Wb : (gate == 2) ? Wc : Wd;
    const float* bsel = (gate == 0) ? ba : (gate == 1) ? bbi : (gate == 2) ? bc : bd;
    int ncolbase = (ntile * 64) % wN;

    // A loader: 64 rows x 16 k, float4 along k
    int a_r = tid >> 2;
    int a_k = (tid & 3) * 4;
    int grow = mtile * 64 + a_r;
    const float* aptr;
    if (tb_mode) {
        int t = grow >> 5, b = grow & 31;
        aptr = A + ((size_t)(b * TT + t)) * DD;
    } else {
        aptr = A + (size_t)grow * DD;
    }
    // B loader: 16 k x 64 n, float4 along n
    int b_k = tid >> 4;
    int b_n = (tid & 15) * 4;

    int tx = tid & 15, ty = tid >> 4;
    float acc[4][4];
#pragma unroll
    for (int i = 0; i < 4; i++)
#pragma unroll
        for (int j = 0; j < 4; j++) acc[i][j] = 0.f;

    for (int k0 = 0; k0 < DD; k0 += 16) {
        float4 av = *(const float4*)(aptr + k0 + a_k);
        float4 bv = *(const float4*)(Wsel + (size_t)(k0 + b_k) * wstride + ncolbase + b_n);
        __syncthreads();
        As[a_k + 0][a_r] = av.x; As[a_k + 1][a_r] = av.y;
        As[a_k + 2][a_r] = av.z; As[a_k + 3][a_r] = av.w;
        *(float4*)&Bs[b_k][b_n] = bv;
        __syncthreads();
#pragma unroll
        for (int kk = 0; kk < 16; kk++) {
            float4 a4 = *(float4*)&As[kk][ty * 4];
            float4 b4 = *(float4*)&Bs[kk][tx * 4];
            float aa[4] = {a4.x, a4.y, a4.z, a4.w};
            float bb4[4] = {b4.x, b4.y, b4.z, b4.w};
#pragma unroll
            for (int i = 0; i < 4; i++)
#pragma unroll
                for (int j = 0; j < 4; j++) acc[i][j] += aa[i] * bb4[j];
        }
    }
#pragma unroll
    for (int i = 0; i < 4; i++) {
        int gr = mtile * 64 + ty * 4 + i;
        float4 v;
        v.x = acc[i][0] + bsel[(ncolbase + tx * 4 + 0) % wN];
        v.y = acc[i][1] + bsel[(ncolbase + tx * 4 + 1) % wN];
        v.z = acc[i][2] + bsel[(ncolbase + tx * 4 + 2) % wN];
        v.w = acc[i][3] + bsel[(ncolbase + tx * 4 + 3) % wN];
        *(float4*)(Out + (size_t)gr * Ncols + ntile * 64 + tx * 4) = v;
    }
}

// ---------------- persistent recurrent kernel ----------------
__global__ void __launch_bounds__(256) recur_kernel(
    const float* __restrict__ context,
    const float* __restrict__ mask,
    const int*   __restrict__ cmask,
    const float* __restrict__ Ui, const float* __restrict__ Uf,
    const float* __restrict__ Uc, const float* __restrict__ Uo,
    const float* __restrict__ Ci, const float* __restrict__ Cf,
    const float* __restrict__ Cc, const float* __restrict__ Co,
    const float* __restrict__ W1h, const float* __restrict__ W2,
    const float* __restrict__ b2,
    float* __restrict__ out, int nb)
{
    __shared__ float sh[2048];      // h (phase1, 4 b) or ctx (phase2, 4 b)
    __shared__ float s_part[1024];  // cross k-split partials
    __shared__ float s_att[AA];
    __shared__ float s_e[LL];
    __shared__ float s_misc;

    const int tid = threadIdx.x;
    const int bid = blockIdx.x;
    float* out_h = out;
    float* out_c = out + (size_t)BB * TT * HH;
    float* out_x = out + (size_t)2 * BB * TT * HH;
    const float b2v = b2[0];

    for (int t = 0; t < TT; t++) {
        if (bid < BB) {
            // ===================== attention for b = bid =====================
            int b = bid;
            if (t == 0) {
                sh[tid] = 0.f; sh[tid + 256] = 0.f;
            } else {
                sh[tid]       = g_hbuf[b * HH + tid];
                sh[tid + 256] = g_hbuf[b * HH + tid + 256];
            }
            __syncthreads();
            // att_h[a] = h . W1h[:,a]
            float acc = 0.f;
            if (t > 0) {
                const float* w = W1h + tid;
#pragma unroll 8
                for (int k = 0; k < HH; k++)
                    acc += sh[k] * w[(size_t)k * AA];
            }
            s_att[tid] = acc;
            __syncthreads();
            // scores per l (warp-per-l)
            int warp = tid >> 5, lane = tid & 31;
            const float* ctb = g_ctr + (size_t)b * LL * AA;
            for (int l = warp; l < LL; l += 8) {
                float p = 0.f;
                const float* ct = ctb + (size_t)l * AA;
#pragma unroll
                for (int a = lane; a < AA; a += 32)
                    p += tanhf(ct[a] + s_att[a]) * W2[a];
#pragma unroll
                for (int o = 16; o > 0; o >>= 1) p += __shfl_xor_sync(0xffffffffu, p, o);
                if (lane == 0)
                    s_e[l] = __expf(p + b2v) * (float)cmask[b * LL + l];
            }
            __syncthreads();
            if (tid < 32) {
                float v = s_e[tid] + s_e[tid + 32];
#pragma unroll
                for (int o = 16; o > 0; o >>= 1) v += __shfl_xor_sync(0xffffffffu, v, o);
                if (tid == 0) s_misc = v;
            }
            __syncthreads();
            float rs = 1.0f / s_misc;
            // ctx_vec -> ctxs output row t (read by phase2 after barrier)
            const float* cb = context + (size_t)b * LL * DD;
            float cv0 = 0.f, cv1 = 0.f;
#pragma unroll 4
            for (int l = 0; l < LL; l++) {
                float al = s_e[l] * rs;
                cv0 += al * cb[(size_t)l * DD + tid];
                cv1 += al * cb[(size_t)l * DD + tid + 256];
            }
            float* oc = out_x + ((size_t)b * TT + t) * DD;
            oc[tid] = cv0; oc[tid + 256] = cv1;
        } else {
            // ================ phase 1 GEMM: g = xg[t] + h@U ==================
            int NG = nb - BB;
            for (int task = bid - BB; task < 256; task += NG) {
                int ctile = task & 31;     // 32 col-tiles of 64 (gate-aligned)
                int btile = task >> 5;     // 8 b-tiles of 4
                int col0 = ctile * 64;
                int b0 = btile * 4;
                __syncthreads();
                if (t > 0) {
                    for (int i = tid; i < 2048; i += 256)
                        sh[i] = g_hbuf[(b0 + (i >> 9)) * HH + (i & 511)];
                }
                __syncthreads();
                int cp = tid & 31;         // 2 cols per thread (float2 weights)
                int bq = (tid >> 5) & 3;
                int kh = tid >> 7;         // k-half
                int col = col0 + cp * 2;
                int gate = col >> 9;
                int ch = col & 511;
                const float* U = (gate == 0) ? Ui : (gate == 1) ? Uf : (gate == 2) ? Uc : Uo;
                float a0 = 0.f, a1 = 0.f;
                if (t > 0) {
                    const float* hrow = sh + bq * 512 + kh * 256;
                    const float* wp = U + (size_t)(kh * 256) * HH + ch;
#pragma unroll 8
                    for (int kk = 0; kk < 256; kk++) {
                        float hv = hrow[kk];
                        float2 w2v = *(const float2*)(wp + (size_t)kk * HH);
                        a0 += hv * w2v.x; a1 += hv * w2v.y;
                    }
                }
                int sidx = (bq * 32 + cp) * 2;
                if (kh == 1) { s_part[sidx] = a0; s_part[sidx + 1] = a1; }
                __syncthreads();
                if (kh == 0) {
                    a0 += s_part[sidx]; a1 += s_part[sidx + 1];
                    int b = b0 + bq;
                    const float* xg = g_xg + ((size_t)t * BB + b) * NCOL + col;
                    a0 += xg[0]; a1 += xg[1];
                    float* gb = g_gbuf + (size_t)b * NCOL + col;
                    gb[0] = a0; gb[1] = a1;
                }
            }
        }
        grid_barrier((unsigned)nb);

        // ============ phase 2: g += ctx@C, fused LSTM pointwise ============
        for (int task = bid; task < 256; task += nb) {
            int htile = task & 31;   // 32 h-col tiles of 16
            int btile = task >> 5;   // 8 b-tiles of 4
            int h0 = htile * 16;
            int b0 = btile * 4;
            __syncthreads();
            for (int i = tid; i < 2048; i += 256)
                sh[i] = out_x[((size_t)(b0 + (i >> 9)) * TT + t) * DD + (i & 511)];
            __syncthreads();
            int hc = tid & 15;
            int bq = (tid >> 4) & 3;
            int kq = tid >> 6;        // k-quarter
            int col = h0 + hc;
            int b = b0 + bq;
            float ai = 0.f, af = 0.f, ac = 0.f, ao = 0.f;
            const float* crow = sh + bq * 512 + kq * 128;
            const float* pCi = Ci + (size_t)(kq * 128) * HH + col;
            const float* pCf = Cf + (size_t)(kq * 128) * HH + col;
            const float* pCc = Cc + (size_t)(kq * 128) * HH + col;
            const float* pCo = Co + (size_t)(kq * 128) * HH + col;
#pragma unroll 4
            for (int kk = 0; kk < 128; kk++) {
                float cv = crow[kk];
                size_t o = (size_t)kk * HH;
                ai += cv * pCi[o];
                af += cv * pCf[o];
                ac += cv * pCc[o];
                ao += cv * pCo[o];
            }
            int sl = (bq * 16 + hc) * 4;
            s_part[kq * 256 + sl + 0] = ai;
            s_part[kq * 256 + sl + 1] = af;
            s_part[kq * 256 + sl + 2] = ac;
            s_part[kq * 256 + sl + 3] = ao;
            __syncthreads();
            if (kq == 0) {
#pragma unroll
                for (int q = 1; q < 4; q++) {
                    ai += s_part[q * 256 + sl + 0];
                    af += s_part[q * 256 + sl + 1];
                    ac += s_part[q * 256 + sl + 2];
                    ao += s_part[q * 256 + sl + 3];
                }
                const float* gbb = g_gbuf + (size_t)b * NCOL;
                ai += gbb[col];
                af += gbb[512 + col];
                ac += gbb[1024 + col];
                ao += gbb[1536 + col];
                float iv = 1.0f / (1.0f + __expf(-ai));
                float fv = 1.0f / (1.0f + __expf(-af));
                float gv = tanhf(ac);
                float ov = 1.0f / (1.0f + __expf(-ao));
                float cprev = 0.f, hprev = 0.f;
                if (t > 0) {
                    cprev = out_c[((size_t)b * TT + (t - 1)) * HH + col];
                    hprev = out_h[((size_t)b * TT + (t - 1)) * HH + col];
                }
                float m = mask[b * TT + t];
                float cn = fv * cprev + iv * gv;
                float hn = ov * tanhf(cn);
                hn = (1.f - m) * hprev + m * hn;
                cn = (1.f - m) * cprev + m * cn;
                out_h[((size_t)b * TT + t) * HH + col] = hn;
                out_c[((size_t)b * TT + t) * HH + col] = cn;
                g_hbuf[b * HH + col] = hn;
            }
        }
        grid_barrier((unsigned)nb);
    }
}

// ---------------- host launcher ----------------
extern "C" void kernel_launch(void* const* d_in, const int* in_sizes, int n_in,
                              void* d_out, int out_size) {
    (void)in_sizes; (void)n_in; (void)out_size;
    const float* X    = (const float*)d_in[0];
    const float* ctx  = (const float*)d_in[1];
    const float* mask = (const float*)d_in[2];
    const int*   cm   = (const int*)d_in[3];
    const float* W[4]; const float* U[4]; const float* C[4]; const float* bi[4];
    for (int g = 0; g < 4; g++) {
        W[g]  = (const float*)d_in[4 + 4 * g];
        U[g]  = (const float*)d_in[5 + 4 * g];
        C[g]  = (const float*)d_in[6 + 4 * g];
        bi[g] = (const float*)d_in[7 + 4 * g];
    }
    const float* attW1c = (const float*)d_in[20];
    const float* attW1h = (const float*)d_in[21];
    const float* attB1  = (const float*)d_in[22];
    const float* attW2  = (const float*)d_in[23];
    const float* attB2  = (const float*)d_in[24];
    float* out = (float*)d_out;

    float* xg_ptr = nullptr; float* ctr_ptr = nullptr;
    cudaGetSymbolAddress((void**)&xg_ptr, g_xg);
    cudaGetSymbolAddress((void**)&ctr_ptr, g_ctr);

    // xg = X@W_{i,f,c,o} + b : M=4096 (t-major rows), N=2048
    dim3 grid1(NCOL / 64, (TT * BB) / 64);
    gemm_proj<<<grid1, 256>>>(X, W[0], W[1], W[2], W[3],
                              bi[0], bi[1], bi[2], bi[3],
                              xg_ptr, NCOL, 512, 512, 1);
    // ctx_trans = context@att_ctx_W1 + b1 : M=2048, N=256
    dim3 grid2(AA / 64, (BB * LL) / 64);
    gemm_proj<<<grid2, 256>>>(ctx, attW1c, attW1c, attW1c, attW1c,
                              attB1, attB1, attB1, attB1,
                              ctr_ptr, AA, AA, AA, 0);

    int dev = 0;
    cudaGetDevice(&dev);
    int nsm = 148;
    cudaDeviceGetAttribute(&nsm, cudaDevAttrMultiProcessorCount, dev);
    if (nsm < 40) nsm = 40;       // need >= 33 (32 attention + >=1 GEMM block)
    if (nsm > 256) nsm = 256;
    recur_kernel<<<nsm, 256>>>(ctx, mask, cm,
                               U[0], U[1], U[2], U[3],
                               C[0], C[1], C[2], C[3],
                               attW1h, attW2, attB2, out, nsm);
}

// round 3
// speedup vs baseline: 2.2840x; 2.2840x over previous
#include <cuda_runtime.h>
#include <cstdint>
#include <cstddef>

#define BB 32
#define TT 128
#define LL 64
#define HH 512
#define AA 256
#define DD 512
#define NCOL 2048

// ---------------- device scratch (no cudaMalloc allowed) ----------------
__device__ float g_xg[(size_t)TT * BB * NCOL];   // [t][b][col] = X@W + b
__device__ float g_ctr[(size_t)BB * LL * AA];    // ctx_trans = context@W1c + b1
__device__ float g_gbuf[(size_t)NCOL * BB];      // [col][b] xg + h@U
__device__ float g_hT[(size_t)HH * BB];          // h(t) transposed [k][b]
__device__ float g_cT[(size_t)DD * BB];          // ctx_vec(t) transposed [k][b]
__device__ unsigned int g_bar_count = 0;
__device__ unsigned int g_bar_gen = 0;
__device__ unsigned int g_task = 0;

// ---------------- grid barrier (sense-reversing, replay-safe) ----------------
__device__ __forceinline__ void grid_barrier(unsigned int nb) {
    __syncthreads();
    if (threadIdx.x == 0) {
        __threadfence();
        volatile unsigned int* vgen = &g_bar_gen;
        unsigned int gen = *vgen;
        unsigned int old = atomicAdd(&g_bar_count, 1u);
        if (old == nb - 1u) {
            g_bar_count = 0u;
            __threadfence();
            atomicAdd(&g_bar_gen, 1u);
        } else {
            while (*vgen == gen) { }
            __threadfence();
        }
    }
    __syncthreads();
}

__device__ __forceinline__ float fast_tanh(float x) {
    float e = __expf(2.0f * x);
    return 1.0f - __fdividef(2.0f, e + 1.0f);
}
__device__ __forceinline__ float fast_sig(float x) {
    return __fdividef(1.0f, 1.0f + __expf(-x));
}

// ---------------- prologue GEMM (unchanged from R1) ----------------
__global__ void __launch_bounds__(256) gemm_proj(
    const float* __restrict__ A,
    const float* __restrict__ Wa, const float* __restrict__ Wb,
    const float* __restrict__ Wc, const float* __restrict__ Wd,
    const float* __restrict__ ba, const float* __restrict__ bbi,
    const float* __restrict__ bc, const float* __restrict__ bd,
    float* __restrict__ Out, int Ncols, int wN, int wstride, int tb_mode)
{
    __shared__ float As[16][64];
    __shared__ float Bs[16][64];
    int tid = threadIdx.x;
    int ntile = blockIdx.x, mtile = blockIdx.y;

    int gate = (ntile * 64) / 512;
    const float* Wsel = (gate == 0) ? Wa : (gate == 1) ? Wb : (gate == 2) ? Wc : Wd;
    const float* bsel = (gate == 0) ? ba : (gate == 1) ? bbi : (gate == 2) ? bc : bd;
    int ncolbase = (ntile * 64) % wN;

    int a_r = tid >> 2;
    int a_k = (tid & 3) * 4;
    int grow = mtile * 64 + a_r;
    const float* aptr;
    if (tb_mode) {
        int t = grow >> 5, b = grow & 31;
        aptr = A + ((size_t)(b * TT + t)) * DD;
    } else {
        aptr = A + (size_t)grow * DD;
    }
    int b_k = tid >> 4;
    int b_n = (tid & 15) * 4;

    int tx = tid & 15, ty = tid >> 4;
    float acc[4][4];
#pragma unroll
    for (int i = 0; i < 4; i++)
#pragma unroll
        for (int j = 0; j < 4; j++) acc[i][j] = 0.f;

    for (int k0 = 0; k0 < DD; k0 += 16) {
        float4 av = *(const float4*)(aptr + k0 + a_k);
        float4 bv = *(const float4*)(Wsel + (size_t)(k0 + b_k) * wstride + ncolbase + b_n);
        __syncthreads();
        As[a_k + 0][a_r] = av.x; As[a_k + 1][a_r] = av.y;
        As[a_k + 2][a_r] = av.z; As[a_k + 3][a_r] = av.w;
        *(float4*)&Bs[b_k][b_n] = bv;
        __syncthreads();
#pragma unroll
        for (int kk = 0; kk < 16; kk++) {
            float4 a4 = *(float4*)&As[kk][ty * 4];
            float4 b4 = *(float4*)&Bs[kk][tx * 4];
            float aa[4] = {a4.x, a4.y, a4.z, a4.w};
            float bb4[4] = {b4.x, b4.y, b4.z, b4.w};
#pragma unroll
            for (int i = 0; i < 4; i++)
#pragma unroll
                for (int j = 0; j < 4; j++) acc[i][j] += aa[i] * bb4[j];
        }
    }
#pragma unroll
    for (int i = 0; i < 4; i++) {
        int gr = mtile * 64 + ty * 4 + i;
        float4 v;
        v.x = acc[i][0] + bsel[(ncolbase + tx * 4 + 0) % wN];
        v.y = acc[i][1] + bsel[(ncolbase + tx * 4 + 1) % wN];
        v.z = acc[i][2] + bsel[(ncolbase + tx * 4 + 2) % wN];
        v.w = acc[i][3] + bsel[(ncolbase + tx * 4 + 3) % wN];
        *(float4*)(Out + (size_t)gr * Ncols + ntile * 64 + tx * 4) = v;
    }
}

// dynamic smem layout (floats):
//   sT  [16384]  : hT (P1) or ctxT (P2), layout [k][32b]
//   sRed[4096]   : k-split partials / attention scratch
//   sG  [512]    : P2 per-task gate sums for epilogue
//   sW2 [256]    : att_W2 cached
//   sS  [8]      : scalars
#define SMEM_FLOATS (16384 + 4096 + 512 + 256 + 8)

// ---------------- persistent recurrent kernel ----------------
__global__ void __launch_bounds__(256, 1) recur_kernel(
    const float* __restrict__ context,
    const float* __restrict__ mask,
    const int*   __restrict__ cmask,
    const float* __restrict__ U0, const float* __restrict__ U1,
    const float* __restrict__ U2, const float* __restrict__ U3,
    const float* __restrict__ C0, const float* __restrict__ C1,
    const float* __restrict__ C2, const float* __restrict__ C3,
    const float* __restrict__ W1h, const float* __restrict__ W2,
    const float* __restrict__ b2,
    float* __restrict__ out, int nb)
{
    extern __shared__ float smem[];
    float* sT   = smem;
    float* sRed = smem + 16384;
    float* sG   = smem + 16384 + 4096;
    float* sW2  = smem + 16384 + 4096 + 512;
    float* sS   = smem + 16384 + 4096 + 512 + 256;
    __shared__ int s_task;

    const int tid = threadIdx.x;
    const int bid = blockIdx.x;
    float* out_h = out;
    float* out_c = out + (size_t)BB * TT * HH;
    float* out_x = out + (size_t)2 * BB * TT * HH;
    const float b2v = b2[0];

    // reset task counter once per launch, then sync the whole grid
    if (bid == 0 && tid == 0) g_task = 0u;
    if (tid < AA) sW2[tid] = W2[tid];
    grid_barrier((unsigned)nb);

    const int g  = tid & 3;          // gate
    const int bq = (tid >> 2) & 7;   // batch quad
    const int kq = tid >> 5;         // k-eighth (64 k)
    const float* Ug = (g == 0) ? U0 : (g == 1) ? U1 : (g == 2) ? U2 : U3;
    const float* Cg = (g == 0) ? C0 : (g == 1) ? C1 : (g == 2) ? C2 : C3;

    for (int t = 0; t < TT; t++) {
        // ================= PHASE 1: attention + h@U =================
        // load hT into smem (zeros at t==0)
        {
            float4* d4 = (float4*)sT;
            if (t == 0) {
                for (int i = tid; i < 4096; i += 256) d4[i] = make_float4(0.f, 0.f, 0.f, 0.f);
            } else {
                const float4* s4 = (const float4*)g_hT;
                for (int i = tid; i < 4096; i += 256) d4[i] = s4[i];
            }
        }
        unsigned int base1 = (unsigned)(t * 2) << 10;
        __syncthreads();
        if (tid == 0) atomicMax(&g_task, base1);

        while (true) {
            __syncthreads();
            if (tid == 0) s_task = (int)(atomicAdd(&g_task, 1u) - base1);
            __syncthreads();
            int tv = s_task;
            if (tv >= 32 + 256) break;

            if (tv < 32) {
                // ---------- attention for batch b ----------
                int b = tv;
                // matvec att[a] = sum_k h[k] * W1h[k][a]
                {
                    int a4 = (tid & 63) * 4;
                    int kg = tid >> 6;              // 0..3, 128 k each
                    float m0 = 0.f, m1 = 0.f, m2 = 0.f, m3 = 0.f;
                    const float* wp = W1h + (size_t)(kg * 128) * AA + a4;
                    const float* hp = sT + kg * 128 * 32 + b;
#pragma unroll 4
                    for (int kk = 0; kk < 128; kk++) {
                        float hv = *hp;
                        float4 w = *(const float4*)wp;
                        m0 += hv * w.x; m1 += hv * w.y; m2 += hv * w.z; m3 += hv * w.w;
                        wp += AA; hp += 32;
                    }
                    float* mv = sRed + 512;
                    *(float4*)&mv[kg * 256 + a4] = make_float4(m0, m1, m2, m3);
                }
                __syncthreads();
                if (tid < 256) {
                    float* mv = sRed + 512;
                    sRed[tid] = mv[tid] + mv[256 + tid] + mv[512 + tid] + mv[768 + tid];
                }
                __syncthreads();
                // scores per l
                {
                    float* s_att = sRed;
                    float* s_e = sRed + 2048;
                    int warp = tid >> 5, lane = tid & 31;
                    const float* ctb = g_ctr + (size_t)b * LL * AA;
#pragma unroll
                    for (int i = 0; i < 8; i++) {
                        int l = warp + i * 8;
                        const float* ct = ctb + (size_t)l * AA;
                        float p = 0.f;
#pragma unroll
                        for (int j = 0; j < 8; j++) {
                            int a = lane + j * 32;
                            p += fast_tanh(ct[a] + s_att[a]) * sW2[a];
                        }
#pragma unroll
                        for (int o = 16; o > 0; o >>= 1) p += __shfl_xor_sync(0xffffffffu, p, o);
                        if (lane == 0)
                            s_e[l] = __expf(p + b2v) * (float)cmask[b * LL + l];
                    }
                }
                __syncthreads();
                if (tid < 32) {
                    float* s_e = sRed + 2048;
                    float v = s_e[tid] + s_e[tid + 32];
#pragma unroll
                    for (int o = 16; o > 0; o >>= 1) v += __shfl_xor_sync(0xffffffffu, v, o);
                    if (tid == 0) sS[0] = v;
                }
                __syncthreads();
                {
                    float rs = __fdividef(1.0f, sS[0]);
                    float* s_e = sRed + 2048;
                    const float* cb = context + (size_t)b * LL * DD;
                    float cv0 = 0.f, cv1 = 0.f;
#pragma unroll 4
                    for (int l = 0; l < LL; l++) {
                        float al = s_e[l] * rs;
                        cv0 += al * cb[(size_t)l * DD + tid];
                        cv1 += al * cb[(size_t)l * DD + tid + 256];
                    }
                    float* oc = out_x + ((size_t)b * TT + t) * DD;
                    oc[tid] = cv0; oc[tid + 256] = cv1;
                    g_cT[(size_t)tid * 32 + b] = cv0;
                    g_cT[(size_t)(tid + 256) * 32 + b] = cv1;
                }
            } else {
                // ---------- h@U tile: 8 cols (4 gates x 2 ch) x 32 b ----------
                int tile = tv - 32;          // 0..255
                int ch0 = tile * 2;
                float a00 = 0.f, a01 = 0.f, a02 = 0.f, a03 = 0.f;
                float a10 = 0.f, a11 = 0.f, a12 = 0.f, a13 = 0.f;
                if (t > 0) {
                    const float* wp = Ug + (size_t)(kq * 64) * HH + ch0;
                    const float* hp = sT + kq * 64 * 32 + bq * 4;
#pragma unroll 8
                    for (int kk = 0; kk < 64; kk++) {
                        float2 w = *(const float2*)wp;
                        float4 h4 = *(const float4*)hp;
                        a00 += w.x * h4.x; a01 += w.x * h4.y; a02 += w.x * h4.z; a03 += w.x * h4.w;
                        a10 += w.y * h4.x; a11 += w.y * h4.y; a12 += w.y * h4.z; a13 += w.y * h4.w;
                        wp += HH; hp += 32;
                    }
                }
                int ob0 = (g * 2 + 0) * 32 + bq * 4;
                int ob1 = (g * 2 + 1) * 32 + bq * 4;
                *(float4*)&sRed[kq * 256 + ob0] = make_float4(a00, a01, a02, a03);
                *(float4*)&sRed[kq * 256 + ob1] = make_float4(a10, a11, a12, a13);
                __syncthreads();
                // reduce 8 k-partials, add xg, store g_gbuf[col][b]
                {
                    int r = tid;               // 256 outputs
                    float s = 0.f;
#pragma unroll
                    for (int q = 0; q < 8; q++) s += sRed[q * 256 + r];
                    int colIdx = r >> 5, b = r & 31;
                    int gate = colIdx >> 1;
                    int col = gate * 512 + ch0 + (colIdx & 1);
                    s += g_xg[((size_t)t * BB + b) * NCOL + col];
                    g_gbuf[(size_t)col * 32 + b] = s;
                }
            }
        }
        grid_barrier((unsigned)nb);

        // ================= PHASE 2: ctx@C + epilogue =================
        {
            float4* d4 = (float4*)sT;
            const float4* s4 = (const float4*)g_cT;
            for (int i = tid; i < 4096; i += 256) d4[i] = s4[i];
        }
        unsigned int base2 = (unsigned)(t * 2 + 1) << 10;
        __syncthreads();
        if (tid == 0) atomicMax(&g_task, base2);

        while (true) {
            __syncthreads();
            if (tid == 0) s_task = (int)(atomicAdd(&g_task, 1u) - base2);
            __syncthreads();
            int tv = s_task;
            if (tv >= 128) break;

            // tile: 16 cols (4 gates x 4 ch) x 32 b
            int ch0 = tv * 4;
            float acc[4][4];
#pragma unroll
            for (int i = 0; i < 4; i++)
#pragma unroll
                for (int j = 0; j < 4; j++) acc[i][j] = 0.f;
            {
                const float* wp = Cg + (size_t)(kq * 64) * HH + ch0;
                const float* hp = sT + kq * 64 * 32 + bq * 4;
#pragma unroll 8
                for (int kk = 0; kk < 64; kk++) {
                    float4 w = *(const float4*)wp;
                    float4 h4 = *(const float4*)hp;
                    acc[0][0] += w.x * h4.x; acc[0][1] += w.x * h4.y; acc[0][2] += w.x * h4.z; acc[0][3] += w.x * h4.w;
                    acc[1][0] += w.y * h4.x; acc[1][1] += w.y * h4.y; acc[1][2] += w.y * h4.z; acc[1][3] += w.y * h4.w;
                    acc[2][0] += w.z * h4.x; acc[2][1] += w.z * h4.y; acc[2][2] += w.z * h4.z; acc[2][3] += w.z * h4.w;
                    acc[3][0] += w.w * h4.x; acc[3][1] += w.w * h4.y; acc[3][2] += w.w * h4.z; acc[3][3] += w.w * h4.w;
                    wp += HH; hp += 32;
                }
            }
#pragma unroll
            for (int ci = 0; ci < 4; ci++) {
                int ob = (g * 4 + ci) * 32 + bq * 4;
                *(float4*)&sRed[kq * 512 + ob] = make_float4(acc[ci][0], acc[ci][1], acc[ci][2], acc[ci][3]);
            }
            __syncthreads();
            // reduce k-partials into sG[512]
            {
                int r0 = tid, r1 = tid + 256;
                float s0 = 0.f, s1 = 0.f;
#pragma unroll
                for (int q = 0; q < 8; q++) { s0 += sRed[q * 512 + r0]; s1 += sRed[q * 512 + r1]; }
                sG[r0] = s0; sG[r1] = s1;
            }
            __syncthreads();
            // fused LSTM epilogue: 4 ch x 32 b
            if (tid < 128) {
                int chi = tid >> 5, b = tid & 31;
                int ch = ch0 + chi;
                float av[4];
#pragma unroll
                for (int gg = 0; gg < 4; gg++) {
                    int col = gg * 512 + ch;
                    av[gg] = sG[(gg * 4 + chi) * 32 + b] + g_gbuf[(size_t)col * 32 + b];
                }
                float iv = fast_sig(av[0]);
                float fv = fast_sig(av[1]);
                float gv = fast_tanh(av[2]);
                float ov = fast_sig(av[3]);
                float cprev = 0.f, hprev = 0.f;
                if (t > 0) {
                    cprev = out_c[((size_t)b * TT + (t - 1)) * HH + ch];
                    hprev = out_h[((size_t)b * TT + (t - 1)) * HH + ch];
                }
                float m = mask[b * TT + t];
                float cn = fv * cprev + iv * gv;
                float hn = ov * fast_tanh(cn);
                hn = (1.f - m) * hprev + m * hn;
                cn = (1.f - m) * cprev + m * cn;
                out_h[((size_t)b * TT + t) * HH + ch] = hn;
                out_c[((size_t)b * TT + t) * HH + ch] = cn;
                g_hT[(size_t)ch * 32 + b] = hn;
            }
        }
        grid_barrier((unsigned)nb);
    }
}

// ---------------- host launcher ----------------
extern "C" void kernel_launch(void* const* d_in, const int* in_sizes, int n_in,
                              void* d_out, int out_size) {
    (void)in_sizes; (void)n_in; (void)out_size;
    const float* X    = (const float*)d_in[0];
    const float* ctx  = (const float*)d_in[1];
    const float* mask = (const float*)d_in[2];
    const int*   cm   = (const int*)d_in[3];
    const float* W[4]; const float* U[4]; const float* C[4]; const float* bi[4];
    for (int gg = 0; gg < 4; gg++) {
        W[gg]  = (const float*)d_in[4 + 4 * gg];
        U[gg]  = (const float*)d_in[5 + 4 * gg];
        C[gg]  = (const float*)d_in[6 + 4 * gg];
        bi[gg] = (const float*)d_in[7 + 4 * gg];
    }
    const float* attW1c = (const float*)d_in[20];
    const float* attW1h = (const float*)d_in[21];
    const float* attB1  = (const float*)d_in[22];
    const float* attW2  = (const float*)d_in[23];
    const float* attB2  = (const float*)d_in[24];
    float* out = (float*)d_out;

    float* xg_ptr = nullptr; float* ctr_ptr = nullptr;
    cudaGetSymbolAddress((void**)&xg_ptr, g_xg);
    cudaGetSymbolAddress((void**)&ctr_ptr, g_ctr);

    // xg = X@W_{i,f,c,o} + b : rows t-major (t*32+b), N=2048
    dim3 grid1(NCOL / 64, (TT * BB) / 64);
    gemm_proj<<<grid1, 256>>>(X, W[0], W[1], W[2], W[3],
                              bi[0], bi[1], bi[2], bi[3],
                              xg_ptr, NCOL, 512, 512, 1);
    // ctx_trans = context@att_ctx_W1 + b1 : M=2048, N=256
    dim3 grid2(AA / 64, (BB * LL) / 64);
    gemm_proj<<<grid2, 256>>>(ctx, attW1c, attW1c, attW1c, attW1c,
                              attB1, attB1, attB1, attB1,
                              ctr_ptr, AA, AA, AA, 0);

    int dev = 0;
    cudaGetDevice(&dev);
    int nsm = 148;
    cudaDeviceGetAttribute(&nsm, cudaDevAttrMultiProcessorCount, dev);
    if (nsm < 1) nsm = 148;
    if (nsm > 512) nsm = 512;

    size_t smem_bytes = (size_t)SMEM_FLOATS * sizeof(float);
    static bool attr_set = false;
    if (!attr_set) {
        cudaFuncSetAttribute(recur_kernel, cudaFuncAttributeMaxDynamicSharedMemorySize,
                             (int)smem_bytes);
        attr_set = true;
    }
    recur_kernel<<<nsm, 256, smem_bytes>>>(ctx, mask, cm,
                                           U[0], U[1], U[2], U[3],
                                           C[0], C[1], C[2], C[3],
                                           attW1h, attW2, attB2, out, nsm);
}

// round 4
// speedup vs baseline: 2.4554x; 1.0750x over previous
#include <cuda_runtime.h>
#include <cstdint>
#include <cstddef>

#define BB 32
#define TT 128
#define LL 64
#define HH 512
#define AA 256
#define DD 512
#define NCOL 2048

// ---------------- device scratch ----------------
__device__ float g_xg[(size_t)TT * NCOL * BB];     // [t][col][b]
__device__ float g_ctr[(size_t)BB * LL * AA];      // ctx_trans
__device__ float g_tmpC[(size_t)2048 * NCOL];      // ctxC pre-transpose [m][col]
__device__ float g_ctxCT[(size_t)NCOL * 2048];     // ctxC [col][b*64+l]
__device__ float g_Upk[(size_t)4 * 256 * 512 * 2]; // [g][k2][c]{even,odd}
__device__ float g_W1hpk[(size_t)256 * 256 * 2];   // [k2][a]{even,odd}
__device__ float g_gbuf[(size_t)NCOL * BB];        // [col][b] xg + h@U
__device__ float g_hTp[(size_t)256 * BB * 2];      // h pair layout [k2][b][2]
__device__ float g_cprev[(size_t)HH * BB];         // c(t-1) [ch][b]
__device__ float g_aw2[(size_t)32 * 64 * 2];       // a pair layout [l2][b][2]
__device__ float g_zbias[512];
__device__ unsigned int g_bar_count = 0;
__device__ unsigned int g_bar_gen = 0;
__device__ unsigned int g_task = 0;

// ---------------- helpers ----------------
__device__ __forceinline__ void grid_barrier(unsigned int nb) {
    __syncthreads();
    if (threadIdx.x == 0) {
        __threadfence();
        volatile unsigned int* vgen = &g_bar_gen;
        unsigned int gen = *vgen;
        unsigned int old = atomicAdd(&g_bar_count, 1u);
        if (old == nb - 1u) {
            g_bar_count = 0u;
            __threadfence();
            atomicAdd(&g_bar_gen, 1u);
        } else {
            while (*vgen == gen) { }
            __threadfence();
        }
    }
    __syncthreads();
}

__device__ __forceinline__ unsigned long long pk2(float lo, float hi) {
    unsigned long long r;
    asm("mov.b64 %0, {%1,%2};" : "=l"(r) : "f"(lo), "f"(hi));
    return r;
}
__device__ __forceinline__ float2 upk2(unsigned long long v) {
    float2 r;
    asm("mov.b64 {%0,%1}, %2;" : "=f"(r.x), "=f"(r.y) : "l"(v));
    return r;
}
__device__ __forceinline__ unsigned long long fma2(unsigned long long a,
                                                   unsigned long long b,
                                                   unsigned long long c) {
    unsigned long long d;
    asm("fma.rn.f32x2 %0, %1, %2, %3;" : "=l"(d) : "l"(a), "l"(b), "l"(c));
    return d;
}
__device__ __forceinline__ float tanh_ap(float x) {
    float y;
    asm("tanh.approx.f32 %0, %1;" : "=f"(y) : "f"(x));
    return y;
}
__device__ __forceinline__ float sig_ap(float x) {
    return fmaf(tanh_ap(0.5f * x), 0.5f, 0.5f);
}

// ---------------- prologue GEMM ----------------
// tb_mode 0: Out[m][Ncols] normal.  tb_mode 1: rows are t*32+b of X, store Out[(t*Ncols+c)*32+b]
__global__ void __launch_bounds__(256) gemm_proj(
    const float* __restrict__ A,
    const float* __restrict__ Wa, const float* __restrict__ Wb,
    const float* __restrict__ Wc, const float* __restrict__ Wd,
    const float* __restrict__ ba, const float* __restrict__ bbi,
    const float* __restrict__ bc, const float* __restrict__ bd,
    float* __restrict__ Out, int Ncols, int wN, int wstride, int tb_mode)
{
    __shared__ float As[16][64];
    __shared__ float Bs[16][64];
    int tid = threadIdx.x;
    int ntile = blockIdx.x, mtile = blockIdx.y;

    int gate = (ntile * 64) / 512;
    const float* Wsel = (gate == 0) ? Wa : (gate == 1) ? Wb : (gate == 2) ? Wc : Wd;
    const float* bsel = (gate == 0) ? ba : (gate == 1) ? bbi : (gate == 2) ? bc : bd;
    int ncolbase = (ntile * 64) % wN;

    int a_r = tid >> 2;
    int a_k = (tid & 3) * 4;
    int grow = mtile * 64 + a_r;
    const float* aptr;
    if (tb_mode) {
        int t = grow >> 5, b = grow & 31;
        aptr = A + ((size_t)(b * TT + t)) * DD;
    } else {
        aptr = A + (size_t)grow * DD;
    }
    int b_k = tid >> 4;
    int b_n = (tid & 15) * 4;

    int tx = tid & 15, ty = tid >> 4;
    float acc[4][4];
#pragma unroll
    for (int i = 0; i < 4; i++)
#pragma unroll
        for (int j = 0; j < 4; j++) acc[i][j] = 0.f;

    for (int k0 = 0; k0 < DD; k0 += 16) {
        float4 av = *(const float4*)(aptr + k0 + a_k);
        float4 bv = *(const float4*)(Wsel + (size_t)(k0 + b_k) * wstride + ncolbase + b_n);
        __syncthreads();
        As[a_k + 0][a_r] = av.x; As[a_k + 1][a_r] = av.y;
        As[a_k + 2][a_r] = av.z; As[a_k + 3][a_r] = av.w;
        *(float4*)&Bs[b_k][b_n] = bv;
        __syncthreads();
#pragma unroll
        for (int kk = 0; kk < 16; kk++) {
            float4 a4 = *(float4*)&As[kk][ty * 4];
            float4 b4 = *(float4*)&Bs[kk][tx * 4];
            float aa[4] = {a4.x, a4.y, a4.z, a4.w};
            float bb4[4] = {b4.x, b4.y, b4.z, b4.w};
#pragma unroll
            for (int i = 0; i < 4; i++)
#pragma unroll
                for (int j = 0; j < 4; j++) acc[i][j] += aa[i] * bb4[j];
        }
    }
#pragma unroll
    for (int i = 0; i < 4; i++) {
        int gr = mtile * 64 + ty * 4 + i;
        float bv0 = bsel[(ncolbase + tx * 4 + 0) % wN];
        float bv1 = bsel[(ncolbase + tx * 4 + 1) % wN];
        float bv2 = bsel[(ncolbase + tx * 4 + 2) % wN];
        float bv3 = bsel[(ncolbase + tx * 4 + 3) % wN];
        if (tb_mode) {
            int t = gr >> 5, b = gr & 31;
            size_t cb = (size_t)t * Ncols + ntile * 64 + tx * 4;
            Out[(cb + 0) * 32 + b] = acc[i][0] + bv0;
            Out[(cb + 1) * 32 + b] = acc[i][1] + bv1;
            Out[(cb + 2) * 32 + b] = acc[i][2] + bv2;
            Out[(cb + 3) * 32 + b] = acc[i][3] + bv3;
        } else {
            float4 v = make_float4(acc[i][0] + bv0, acc[i][1] + bv1,
                                   acc[i][2] + bv2, acc[i][3] + bv3);
            *(float4*)(Out + (size_t)gr * Ncols + ntile * 64 + tx * 4) = v;
        }
    }
}

// ---------------- 2048x2048 transpose: out[col][m] = in[m][col] ----------------
__global__ void __launch_bounds__(256) transpose2048(const float* __restrict__ in,
                                                     float* __restrict__ out) {
    __shared__ float tile[32][33];
    int x = blockIdx.x * 32 + threadIdx.x;
    int y0 = blockIdx.y * 32 + threadIdx.y;
#pragma unroll
    for (int j = 0; j < 32; j += 8)
        tile[threadIdx.y + j][threadIdx.x] = in[(size_t)(y0 + j) * 2048 + x];
    __syncthreads();
    int x2 = blockIdx.y * 32 + threadIdx.x;
    int y2 = blockIdx.x * 32 + threadIdx.y;
#pragma unroll
    for (int j = 0; j < 32; j += 8)
        out[(size_t)(y2 + j) * 2048 + x2] = tile[threadIdx.x][threadIdx.y + j];
}

// ---------------- weight repack into k-parity pairs ----------------
__global__ void __launch_bounds__(256) repack_weights(
    const float* __restrict__ U0, const float* __restrict__ U1,
    const float* __restrict__ U2, const float* __restrict__ U3)
{
    int i = blockIdx.x * 256 + threadIdx.x;   // over 4*256*512
    if (i < 4 * 256 * 512) {
        int g = i >> 17;
        int r = i & 131071;
        int k2 = r >> 9, c = r & 511;
        const float* Ug = (g == 0) ? U0 : (g == 1) ? U1 : (g == 2) ? U2 : U3;
        g_Upk[(size_t)i * 2 + 0] = Ug[(size_t)(2 * k2) * 512 + c];
        g_Upk[(size_t)i * 2 + 1] = Ug[(size_t)(2 * k2 + 1) * 512 + c];
    }
}
__global__ void __launch_bounds__(256) repack_w1h(const float* __restrict__ W1h) {
    int i = blockIdx.x * 256 + threadIdx.x;   // over 256*256
    if (i < 256 * 256) {
        int k2 = i >> 8, a = i & 255;
        g_W1hpk[(size_t)i * 2 + 0] = W1h[(size_t)(2 * k2) * AA + a];
        g_W1hpk[(size_t)i * 2 + 1] = W1h[(size_t)(2 * k2 + 1) * AA + a];
    }
}

// dynamic smem (floats): sTp[16384] | sRed[4096] | sG[512] | sW2[256] | sS[8]
#define SMEM_FLOATS (16384 + 4096 + 512 + 256 + 8)

// ---------------- persistent recurrent kernel ----------------
__global__ void __launch_bounds__(256, 1) recur_kernel(
    const float* __restrict__ context,
    const float* __restrict__ mask,
    const int*   __restrict__ cmask,
    const float* __restrict__ W2, const float* __restrict__ b2,
    float* __restrict__ out, int nb)
{
    extern __shared__ float smem[];
    float* sTp  = smem;                 // 16384 (h pair tile, P1)
    float* sRed = smem + 16384;         // 4096 (scratch / a-pairs in P2)
    float* sG   = smem + 16384 + 4096;  // 512
    float* sW2  = smem + 16384 + 4096 + 512;
    float* sS   = smem + 16384 + 4096 + 512 + 256;
    __shared__ int s_task;

    const int tid = threadIdx.x;
    const int bid = blockIdx.x;
    float* out_h = out;
    float* out_c = out + (size_t)BB * TT * HH;
    float* out_x = out + (size_t)2 * BB * TT * HH;
    const float b2v = b2[0];

    if (bid == 0 && tid == 0) g_task = 0u;
    if (tid < AA) sW2[tid] = W2[tid];
    grid_barrier((unsigned)nb);

    // thread roles for h@U tiles
    const int g  = tid & 3;
    const int bq = (tid >> 2) & 7;
    const int kq = tid >> 5;            // 8 k-eighths (32 k-pairs each)

    for (int t = 0; t < TT; t++) {
        // ================= PHASE 1: attention + h@U =================
        {
            float4* d4 = (float4*)sTp;
            if (t == 0) {
                for (int i = tid; i < 4096; i += 256) d4[i] = make_float4(0.f, 0.f, 0.f, 0.f);
            } else {
                const float4* s4 = (const float4*)g_hTp;
                for (int i = tid; i < 4096; i += 256) d4[i] = s4[i];
            }
        }
        unsigned int base1 = (unsigned)(t * 2) << 10;
        __syncthreads();
        if (tid == 0) atomicMax(&g_task, base1);

        while (true) {
            __syncthreads();
            if (tid == 0) s_task = (int)(atomicAdd(&g_task, 1u) - base1);
            __syncthreads();
            int tv = s_task;
            if (tv >= 32 + 256) break;

            if (tv < 32) {
                // ---------- attention for batch b ----------
                int b = tv;
                float* sAtt = sRed;              // 256
                float* sMv  = sRed + 256;        // 1024
                float* sE   = sRed + 1280;       // 64
                float* sCtx = sRed + 1408;       // 512
                // matvec att[a] = sum_k h[k]*W1h[k][a], k-pair packed
                {
                    int a4 = (tid & 63) * 4;
                    int kg = tid >> 6;           // 4 groups x 64 k-pairs
                    unsigned long long acc0 = 0, acc1 = 0, acc2 = 0, acc3 = 0;
                    const float* wp = g_W1hpk + ((size_t)(kg * 64) * 256 + a4) * 2;
                    const float* hp = sTp + (kg * 64) * 64 + b * 2;
#pragma unroll 4
                    for (int p = 0; p < 64; p++) {
                        float2 hv = *(const float2*)hp;
                        unsigned long long hpair = pk2(hv.x, hv.y);
                        float4 w01 = *(const float4*)(wp);
                        float4 w23 = *(const float4*)(wp + 4);
                        acc0 = fma2(pk2(w01.x, w01.y), hpair, acc0);
                        acc1 = fma2(pk2(w01.z, w01.w), hpair, acc1);
                        acc2 = fma2(pk2(w23.x, w23.y), hpair, acc2);
                        acc3 = fma2(pk2(w23.z, w23.w), hpair, acc3);
                        wp += 512; hp += 64;
                    }
                    float2 r0 = upk2(acc0), r1 = upk2(acc1), r2 = upk2(acc2), r3 = upk2(acc3);
                    *(float4*)&sMv[kg * 256 + a4] =
                        make_float4(r0.x + r0.y, r1.x + r1.y, r2.x + r2.y, r3.x + r3.y);
                }
                __syncthreads();
                sAtt[tid] = sMv[tid] + sMv[256 + tid] + sMv[512 + tid] + sMv[768 + tid];
                __syncthreads();
                // scores
                {
                    int warp = tid >> 5, lane = tid & 31;
                    const float* ctb = g_ctr + (size_t)b * LL * AA;
#pragma unroll
                    for (int i = 0; i < 8; i++) {
                        int l = warp + i * 8;
                        const float* ct = ctb + (size_t)l * AA;
                        float p = 0.f;
#pragma unroll
                        for (int j = 0; j < 8; j++) {
                            int a = lane + j * 32;
                            p += tanh_ap(ct[a] + sAtt[a]) * sW2[a];
                        }
#pragma unroll
                        for (int o = 16; o > 0; o >>= 1) p += __shfl_xor_sync(0xffffffffu, p, o);
                        if (lane == 0)
                            sE[l] = __expf(p + b2v) * (float)cmask[b * LL + l];
                    }
                }
                __syncthreads();
                if (tid < 32) {
                    float v = sE[tid] + sE[tid + 32];
#pragma unroll
                    for (int o = 16; o > 0; o >>= 1) v += __shfl_xor_sync(0xffffffffu, v, o);
                    if (tid == 0) sS[0] = v;
                }
                __syncthreads();
                float rs = __fdividef(1.0f, sS[0]);
                if (tid < 64)
                    g_aw2[(tid >> 1) * 64 + b * 2 + (tid & 1)] = sE[tid] * rs;
                // ctx_vec (weighted sum of context rows), float4, l split in halves
                {
                    int d4i = (tid & 127) * 4;
                    int lh = tid >> 7;
                    const float* cb = context + ((size_t)b * LL + lh * 32) * DD + d4i;
                    float c0 = 0.f, c1 = 0.f, c2 = 0.f, c3 = 0.f;
#pragma unroll 4
                    for (int l = 0; l < 32; l++) {
                        float al = sE[lh * 32 + l] * rs;
                        float4 cv = *(const float4*)(cb + (size_t)l * DD);
                        c0 += al * cv.x; c1 += al * cv.y; c2 += al * cv.z; c3 += al * cv.w;
                    }
                    if (lh == 1) *(float4*)&sCtx[d4i] = make_float4(c0, c1, c2, c3);
                    __syncthreads();
                    if (lh == 0) {
                        float4 o4 = make_float4(c0 + sCtx[d4i], c1 + sCtx[d4i + 1],
                                                c2 + sCtx[d4i + 2], c3 + sCtx[d4i + 3]);
                        *(float4*)(out_x + ((size_t)b * TT + t) * DD + d4i) = o4;
                    }
                }
            } else {
                // ---------- h@U tile: (2 ch x 4 gates) x 32 b, k-pair packed ----------
                int tile = tv - 32;              // 0..255
                int ch0 = tile * 2;
                unsigned long long ac[2][4];
#pragma unroll
                for (int i = 0; i < 2; i++)
#pragma unroll
                    for (int j = 0; j < 4; j++) ac[i][j] = 0;
                if (t > 0) {
                    const float* wp = g_Upk + (((size_t)g * 256 + kq * 32) * 512 + ch0) * 2;
                    const float* hp = sTp + (kq * 32) * 64 + bq * 8;
#pragma unroll 8
                    for (int p = 0; p < 32; p++) {
                        float4 wv = *(const float4*)wp;           // c0 pair, c1 pair
                        float4 h01 = *(const float4*)hp;          // b0 pair, b1 pair
                        float4 h23 = *(const float4*)(hp + 4);    // b2 pair, b3 pair
                        unsigned long long w0 = pk2(wv.x, wv.y);
                        unsigned long long w1 = pk2(wv.z, wv.w);
                        unsigned long long hb0 = pk2(h01.x, h01.y);
                        unsigned long long hb1 = pk2(h01.z, h01.w);
                        unsigned long long hb2 = pk2(h23.x, h23.y);
                        unsigned long long hb3 = pk2(h23.z, h23.w);
                        ac[0][0] = fma2(w0, hb0, ac[0][0]);
                        ac[0][1] = fma2(w0, hb1, ac[0][1]);
                        ac[0][2] = fma2(w0, hb2, ac[0][2]);
                        ac[0][3] = fma2(w0, hb3, ac[0][3]);
                        ac[1][0] = fma2(w1, hb0, ac[1][0]);
                        ac[1][1] = fma2(w1, hb1, ac[1][1]);
                        ac[1][2] = fma2(w1, hb2, ac[1][2]);
                        ac[1][3] = fma2(w1, hb3, ac[1][3]);
                        wp += 1024; hp += 64;
                    }
                }
#pragma unroll
                for (int ci = 0; ci < 2; ci++) {
                    float2 r0 = upk2(ac[ci][0]), r1 = upk2(ac[ci][1]);
                    float2 r2 = upk2(ac[ci][2]), r3 = upk2(ac[ci][3]);
                    *(float4*)&sRed[kq * 256 + (g * 2 + ci) * 32 + bq * 4] =
                        make_float4(r0.x + r0.y, r1.x + r1.y, r2.x + r2.y, r3.x + r3.y);
                }
                __syncthreads();
                {
                    int colIdx = tid >> 5, b = tid & 31;
                    float s = 0.f;
#pragma unroll
                    for (int q = 0; q < 8; q++) s += sRed[q * 256 + tid];
                    int gate = colIdx >> 1;
                    int col = gate * 512 + ch0 + (colIdx & 1);
                    s += g_xg[((size_t)t * NCOL + col) * 32 + b];
                    g_gbuf[(size_t)col * 32 + b] = s;
                }
            }
        }
        grid_barrier((unsigned)nb);

        // ================= PHASE 2: a.ctxC + epilogue =================
        {   // load a-pairs into smem (2048 floats)
            float4* d4 = (float4*)sRed;
            const float4* s4 = (const float4*)g_aw2;
            for (int i = tid; i < 512; i += 256) d4[i] = s4[i];
        }
        unsigned int base2 = (unsigned)(t * 2 + 1) << 10;
        __syncthreads();
        if (tid == 0) atomicMax(&g_task, base2);

        while (true) {
            __syncthreads();
            if (tid == 0) s_task = (int)(atomicAdd(&g_task, 1u) - base2);
            __syncthreads();
            int tv = s_task;
            if (tv >= 128) break;

            int ch0 = tv * 4;
            int idx = tid & 127;
            int chi = idx >> 5, b = idx & 31;
            int half = tid >> 7;                 // l-half (32 l each)
            int ch = ch0 + chi;

            // preload 16 a-pairs for (b, half)
            unsigned long long apr[16];
#pragma unroll
            for (int j = 0; j < 16; j++) {
                float2 av = *(const float2*)&sRed[(half * 16 + j) * 64 + b * 2];
                apr[j] = pk2(av.x, av.y);
            }
            float gsum[4];
#pragma unroll
            for (int g2 = 0; g2 < 4; g2++) {
                int col = g2 * 512 + ch;
                const float* cp = g_ctxCT + ((size_t)col * 32 + b) * 64 + half * 32;
                unsigned long long acc = 0;
#pragma unroll
                for (int u = 0; u < 8; u++) {
                    float4 cv = *(const float4*)(cp + u * 4);
                    acc = fma2(pk2(cv.x, cv.y), apr[u * 2 + 0], acc);
                    acc = fma2(pk2(cv.z, cv.w), apr[u * 2 + 1], acc);
                }
                float2 r = upk2(acc);
                gsum[g2] = r.x + r.y;
            }
            if (half == 1) {
#pragma unroll
                for (int g2 = 0; g2 < 4; g2++) sG[idx * 4 + g2] = gsum[g2];
            }
            __syncthreads();
            if (half == 0) {
                float av[4];
#pragma unroll
                for (int g2 = 0; g2 < 4; g2++) {
                    int col = g2 * 512 + ch;
                    av[g2] = gsum[g2] + sG[idx * 4 + g2] + g_gbuf[(size_t)col * 32 + b];
                }
                float iv = sig_ap(av[0]);
                float fv = sig_ap(av[1]);
                float gv = tanh_ap(av[2]);
                float ov = sig_ap(av[3]);
                float cprev = 0.f, hprev = 0.f;
                if (t > 0) {
                    cprev = g_cprev[(size_t)ch * 32 + b];
                    hprev = g_hTp[(size_t)(ch >> 1) * 64 + b * 2 + (ch & 1)];
                }
                float m = mask[b * TT + t];
                float cn = fv * cprev + iv * gv;
                float hn = ov * tanh_ap(cn);
                hn = (1.f - m) * hprev + m * hn;
                cn = (1.f - m) * cprev + m * cn;
                out_h[((size_t)b * TT + t) * HH + ch] = hn;
                out_c[((size_t)b * TT + t) * HH + ch] = cn;
                g_cprev[(size_t)ch * 32 + b] = cn;
                g_hTp[(size_t)(ch >> 1) * 64 + b * 2 + (ch & 1)] = hn;
            }
        }
        grid_barrier((unsigned)nb);
    }
}

// ---------------- host launcher ----------------
extern "C" void kernel_launch(void* const* d_in, const int* in_sizes, int n_in,
                              void* d_out, int out_size) {
    (void)in_sizes; (void)n_in; (void)out_size;
    const float* X    = (const float*)d_in[0];
    const float* ctx  = (const float*)d_in[1];
    const float* mask = (const float*)d_in[2];
    const int*   cm   = (const int*)d_in[3];
    const float* W[4]; const float* U[4]; const float* C[4]; const float* bi[4];
    for (int gg = 0; gg < 4; gg++) {
        W[gg]  = (const float*)d_in[4 + 4 * gg];
        U[gg]  = (const float*)d_in[5 + 4 * gg];
        C[gg]  = (const float*)d_in[6 + 4 * gg];
        bi[gg] = (const float*)d_in[7 + 4 * gg];
    }
    const float* attW1c = (const float*)d_in[20];
    const float* attW1h = (const float*)d_in[21];
    const float* attB1  = (const float*)d_in[22];
    const float* attW2  = (const float*)d_in[23];
    const float* attB2  = (const float*)d_in[24];
    float* out = (float*)d_out;

    float *xg_ptr = nullptr, *ctr_ptr = nullptr, *tmpC_ptr = nullptr,
          *ctxCT_ptr = nullptr, *zb_ptr = nullptr;
    cudaGetSymbolAddress((void**)&xg_ptr, g_xg);
    cudaGetSymbolAddress((void**)&ctr_ptr, g_ctr);
    cudaGetSymbolAddress((void**)&tmpC_ptr, g_tmpC);
    cudaGetSymbolAddress((void**)&ctxCT_ptr, g_ctxCT);
    cudaGetSymbolAddress((void**)&zb_ptr, g_zbias);

    // xg = X@W + b, stored [t][col][b]
    dim3 grid1(NCOL / 64, (TT * BB) / 64);
    gemm_proj<<<grid1, 256>>>(X, W[0], W[1], W[2], W[3],
                              bi[0], bi[1], bi[2], bi[3],
                              xg_ptr, NCOL, 512, 512, 1);
    // ctx_trans = context@att_ctx_W1 + b1
    dim3 grid2(AA / 64, (BB * LL) / 64);
    gemm_proj<<<grid2, 256>>>(ctx, attW1c, attW1c, attW1c, attW1c,
                              attB1, attB1, attB1, attB1,
                              ctr_ptr, AA, AA, AA, 0);
    // ctxC = context@C_g (no bias), [m][col] then transpose to [col][m]
    dim3 grid3(NCOL / 64, 2048 / 64);
    gemm_proj<<<grid3, 256>>>(ctx, C[0], C[1], C[2], C[3],
                              zb_ptr, zb_ptr, zb_ptr, zb_ptr,
                              tmpC_ptr, NCOL, 512, 512, 0);
    transpose2048<<<dim3(64, 64), dim3(32, 8)>>>(tmpC_ptr, ctxCT_ptr);
    repack_weights<<<(4 * 256 * 512 + 255) / 256, 256>>>(U[0], U[1], U[2], U[3]);
    repack_w1h<<<(256 * 256 + 255) / 256, 256>>>(attW1h);

    int dev = 0;
    cudaGetDevice(&dev);
    int nsm = 148;
    cudaDeviceGetAttribute(&nsm, cudaDevAttrMultiProcessorCount, dev);
    if (nsm < 1) nsm = 148;
    if (nsm > 512) nsm = 512;

    size_t smem_bytes = (size_t)SMEM_FLOATS * sizeof(float);
    static bool attr_set = false;
    if (!attr_set) {
        cudaFuncSetAttribute(recur_kernel, cudaFuncAttributeMaxDynamicSharedMemorySize,
                             (int)smem_bytes);
        attr_set = true;
    }
    recur_kernel<<<nsm, 256, smem_bytes>>>(ctx, mask, cm, attW2, attB2, out, nsm);
}

// round 5
// speedup vs baseline: 2.7318x; 1.1125x over previous
#include <cuda_runtime.h>
#include <cstdint>
#include <cstddef>

#define BB 32
#define TT 128
#define LL 64
#define HH 512
#define AA 256
#define DD 512
#define NCOL 2048
#define UCOLS 2304          // 2048 gate cols + 256 att cols
#define NBLK 144            // 2304 / 16
#define WSTRIDE (UCOLS * 2) // floats per k2 row of packed weights

typedef unsigned long long u64;

// ---------------- device scratch ----------------
__device__ float g_xg[(size_t)TT * BB * NCOL];     // [t*32+b][col]
__device__ float g_ctr[(size_t)BB * LL * AA];      // ctx_trans [b*64+l][a]
__device__ float g_ctxC[(size_t)BB * LL * NCOL];   // context@C [b*64+l][col]
__device__ float g_Wpk[(size_t)256 * UCOLS * 2];   // [k2][c]{keven,kodd}
__device__ float g_gbuf[(size_t)BB * NCOL];        // [b][col] xg + h@U
__device__ float g_attv[(size_t)BB * AA];          // [b][a] h@W1h
__device__ float g_hp[(size_t)256 * BB * 2];       // h pairs [k2][b]{keven,kodd}
__device__ float g_cst[(size_t)BB * HH];           // c state [b][ch]
__device__ float g_zbias[512];                     // zeros
__device__ unsigned g_arr[256];                    // barrier arrival flags
__device__ unsigned g_rel;                         // barrier release gen
__device__ unsigned g_epoch;                       // persistent across replays

// ---------------- helpers ----------------
__device__ __forceinline__ u64 pk2(float lo, float hi) {
    u64 r; asm("mov.b64 %0, {%1,%2};" : "=l"(r) : "f"(lo), "f"(hi)); return r;
}
__device__ __forceinline__ float2 upk2(u64 v) {
    float2 r; asm("mov.b64 {%0,%1}, %2;" : "=f"(r.x), "=f"(r.y) : "l"(v)); return r;
}
__device__ __forceinline__ u64 fma2(u64 a, u64 b, u64 c) {
    u64 d; asm("fma.rn.f32x2 %0, %1, %2, %3;" : "=l"(d) : "l"(a), "l"(b), "l"(c)); return d;
}
__device__ __forceinline__ float tanh_ap(float x) {
    float y; asm("tanh.approx.f32 %0, %1;" : "=f"(y) : "f"(x)); return y;
}
__device__ __forceinline__ float sig_ap(float x) {
    return fmaf(tanh_ap(0.5f * x), 0.5f, 0.5f);
}

// flag-based grid barrier: one store per block, block0 gathers, one release word
__device__ __forceinline__ void gbar(int bid, int tid, unsigned gen) {
    __syncthreads();
    if (tid == 0) {
        __threadfence();
        *(volatile unsigned*)&g_arr[bid] = gen;
    }
    if (bid == 0) {
        if (tid < NBLK) {
            while (*(volatile unsigned*)&g_arr[tid] < gen) { }
        }
        __syncthreads();
        if (tid == 0) {
            __threadfence();
            *(volatile unsigned*)&g_rel = gen;
        }
    }
    if (tid == 0) {
        while (*(volatile unsigned*)&g_rel < gen) { }
        __threadfence();
    }
    __syncthreads();
}

// ---------------- prologue GEMM (tb_mode only changes A addressing) ----------------
__global__ void __launch_bounds__(256) gemm_proj(
    const float* __restrict__ A,
    const float* __restrict__ Wa, const float* __restrict__ Wb,
    const float* __restrict__ Wc, const float* __restrict__ Wd,
    const float* __restrict__ ba, const float* __restrict__ bbi,
    const float* __restrict__ bc, const float* __restrict__ bd,
    float* __restrict__ Out, int Ncols, int wN, int wstride, int tb_mode)
{
    __shared__ float As[16][64];
    __shared__ float Bs[16][64];
    int tid = threadIdx.x;
    int ntile = blockIdx.x, mtile = blockIdx.y;

    int gate = (ntile * 64) / 512;
    const float* Wsel = (gate == 0) ? Wa : (gate == 1) ? Wb : (gate == 2) ? Wc : Wd;
    const float* bsel = (gate == 0) ? ba : (gate == 1) ? bbi : (gate == 2) ? bc : bd;
    int ncolbase = (ntile * 64) % wN;

    int a_r = tid >> 2;
    int a_k = (tid & 3) * 4;
    int grow = mtile * 64 + a_r;
    const float* aptr;
    if (tb_mode) {
        int t = grow >> 5, b = grow & 31;
        aptr = A + ((size_t)(b * TT + t)) * DD;
    } else {
        aptr = A + (size_t)grow * DD;
    }
    int b_k = tid >> 4;
    int b_n = (tid & 15) * 4;

    int tx = tid & 15, ty = tid >> 4;
    float acc[4][4];
#pragma unroll
    for (int i = 0; i < 4; i++)
#pragma unroll
        for (int j = 0; j < 4; j++) acc[i][j] = 0.f;

    for (int k0 = 0; k0 < DD; k0 += 16) {
        float4 av = *(const float4*)(aptr + k0 + a_k);
        float4 bv = *(const float4*)(Wsel + (size_t)(k0 + b_k) * wstride + ncolbase + b_n);
        __syncthreads();
        As[a_k + 0][a_r] = av.x; As[a_k + 1][a_r] = av.y;
        As[a_k + 2][a_r] = av.z; As[a_k + 3][a_r] = av.w;
        *(float4*)&Bs[b_k][b_n] = bv;
        __syncthreads();
#pragma unroll
        for (int kk = 0; kk < 16; kk++) {
            float4 a4 = *(float4*)&As[kk][ty * 4];
            float4 b4 = *(float4*)&Bs[kk][tx * 4];
            float aa[4] = {a4.x, a4.y, a4.z, a4.w};
            float bb4[4] = {b4.x, b4.y, b4.z, b4.w};
#pragma unroll
            for (int i = 0; i < 4; i++)
#pragma unroll
                for (int j = 0; j < 4; j++) acc[i][j] += aa[i] * bb4[j];
        }
    }
#pragma unroll
    for (int i = 0; i < 4; i++) {
        int gr = mtile * 64 + ty * 4 + i;
        float4 v;
        v.x = acc[i][0] + bsel[(ncolbase + tx * 4 + 0) % wN];
        v.y = acc[i][1] + bsel[(ncolbase + tx * 4 + 1) % wN];
        v.z = acc[i][2] + bsel[(ncolbase + tx * 4 + 2) % wN];
        v.w = acc[i][3] + bsel[(ncolbase + tx * 4 + 3) % wN];
        *(float4*)(Out + (size_t)gr * Ncols + ntile * 64 + tx * 4) = v;
    }
}

// ---------------- unified weight repack: U gates + W1h, k-parity pairs ----------------
__global__ void __launch_bounds__(256) repack_wpk(
    const float* __restrict__ U0, const float* __restrict__ U1,
    const float* __restrict__ U2, const float* __restrict__ U3,
    const float* __restrict__ W1h)
{
    int i = blockIdx.x * 256 + threadIdx.x;     // over 256*2304
    if (i >= 256 * UCOLS) return;
    int k2 = i / UCOLS;
    int c = i - k2 * UCOLS;
    float e, o;
    if (c < 2048) {
        int g = c >> 9, ch = c & 511;
        const float* Ug = (g == 0) ? U0 : (g == 1) ? U1 : (g == 2) ? U2 : U3;
        e = Ug[(size_t)(2 * k2) * 512 + ch];
        o = Ug[(size_t)(2 * k2 + 1) * 512 + ch];
    } else {
        int a = c - 2048;
        e = W1h[(size_t)(2 * k2) * AA + a];
        o = W1h[(size_t)(2 * k2 + 1) * AA + a];
    }
    g_Wpk[(size_t)i * 2 + 0] = e;
    g_Wpk[(size_t)i * 2 + 1] = o;
}

// dynamic smem: sTp[256*68] pairs (padded) | sRed[2048]  => 19456 floats
#define STP_STRIDE 68
#define SMEM_FLOATS (256 * STP_STRIDE + 2048)

// ---------------- persistent recurrent kernel ----------------
__global__ void __launch_bounds__(256, 1) recur_kernel(
    const float* __restrict__ context,
    const float* __restrict__ mask,
    const int*   __restrict__ cmask,
    const float* __restrict__ W2, const float* __restrict__ b2,
    float* __restrict__ out)
{
    extern __shared__ float smem[];
    float* sTp  = smem;                       // P1: h pairs [k2][b]{e,o}, stride 68
    float* sRed = smem + 256 * STP_STRIDE;    // P1: k-quarter partials [kq][b*16+colL]
    // P2 views (reused after barrier A):
    float* sG    = smem;                      // 2048: a.ctxC gate sums
    float* sAtt  = smem + 2048;               // 256
    float* sW2s  = smem + 2048 + 256;         // 256
    float* sE    = smem + 2048 + 512;         // 64
    float* sA    = smem + 2048 + 576;         // 64
    float* sSum  = smem + 2048 + 640;         // 1

    const int tid = threadIdx.x;
    const int bid = blockIdx.x;
    float* out_h = out;
    float* out_c = out + (size_t)BB * TT * HH;
    float* out_x = out + (size_t)2 * BB * TT * HH;
    const float b2v = b2[0];

    unsigned base = *(volatile unsigned*)&g_epoch;

    const int c0 = bid * 16;
    const int cp = tid & 7;            // col-pair within block (2 cols)
    const int bq = (tid >> 3) & 7;     // batch quad
    const int kq = tid >> 6;           // k-quarter (64 k-pairs)
    const int c  = c0 + cp * 2;

    for (int t = 0; t < TT; t++) {
        // ================= PHASE 1: unified GEMM over h =================
        if (t > 0) {
            const float4* src = (const float4*)g_hp;
            for (int f4 = tid; f4 < 4096; f4 += 256) {
                int k2 = f4 >> 4, off = (f4 & 15) * 4;
                *(float4*)&sTp[k2 * STP_STRIDE + off] = src[f4];
            }
        }
        __syncthreads();

        u64 ac[2][4];
#pragma unroll
        for (int i = 0; i < 2; i++)
#pragma unroll
            for (int j = 0; j < 4; j++) ac[i][j] = 0;
        if (t > 0) {
            const float* wp = g_Wpk + ((size_t)(kq * 64) * UCOLS + c) * 2;
            const float* hp = sTp + (kq * 64) * STP_STRIDE + bq * 8;
#pragma unroll 8
            for (int p = 0; p < 64; p++) {
                float4 wv  = *(const float4*)wp;        // c pair, c+1 pair
                float4 h01 = *(const float4*)hp;        // b0 pair, b1 pair
                float4 h23 = *(const float4*)(hp + 4);  // b2 pair, b3 pair
                u64 w0 = pk2(wv.x, wv.y);
                u64 w1 = pk2(wv.z, wv.w);
                u64 hb0 = pk2(h01.x, h01.y);
                u64 hb1 = pk2(h01.z, h01.w);
                u64 hb2 = pk2(h23.x, h23.y);
                u64 hb3 = pk2(h23.z, h23.w);
                ac[0][0] = fma2(w0, hb0, ac[0][0]);
                ac[0][1] = fma2(w0, hb1, ac[0][1]);
                ac[0][2] = fma2(w0, hb2, ac[0][2]);
                ac[0][3] = fma2(w0, hb3, ac[0][3]);
                ac[1][0] = fma2(w1, hb0, ac[1][0]);
                ac[1][1] = fma2(w1, hb1, ac[1][1]);
                ac[1][2] = fma2(w1, hb2, ac[1][2]);
                ac[1][3] = fma2(w1, hb3, ac[1][3]);
                wp += WSTRIDE; hp += STP_STRIDE;
            }
        }
#pragma unroll
        for (int bi = 0; bi < 4; bi++) {
            float2 r0 = upk2(ac[0][bi]);
            float2 r1 = upk2(ac[1][bi]);
            float2 v = make_float2(r0.x + r0.y, r1.x + r1.y);
            *(float2*)&sRed[kq * 512 + (bq * 4 + bi) * 16 + cp * 2] = v;
        }
        __syncthreads();
#pragma unroll
        for (int o = tid; o < 512; o += 256) {
            float s = sRed[o] + sRed[512 + o] + sRed[1024 + o] + sRed[1536 + o];
            int b = o >> 4, colL = o & 15;
            if (bid < 128) {
                int col = c0 + colL;
                s += g_xg[((size_t)t * BB + b) * NCOL + col];
                g_gbuf[(size_t)b * NCOL + col] = s;
            } else {
                g_attv[b * AA + (c0 - 2048) + colL] = s;
            }
        }
        gbar(bid, tid, base + (unsigned)(2 * t + 1));

        // ================= PHASE 2: per-batch attention + epilogue =================
        if (bid < BB) {
            const int b = bid;
            sAtt[tid] = g_attv[b * AA + tid];
            sW2s[tid] = W2[tid];
            __syncthreads();
            // scores
            {
                int warp = tid >> 5, lane = tid & 31;
#pragma unroll
                for (int i = 0; i < 8; i++) {
                    int l = warp * 8 + i;
                    const float* ct = g_ctr + ((size_t)b * LL + l) * AA;
                    float p = 0.f;
#pragma unroll
                    for (int j = 0; j < 8; j++) {
                        int a = lane + j * 32;
                        p += tanh_ap(ct[a] + sAtt[a]) * sW2s[a];
                    }
#pragma unroll
                    for (int o = 16; o > 0; o >>= 1) p += __shfl_xor_sync(0xffffffffu, p, o);
                    if (lane == 0)
                        sE[l] = __expf(p + b2v) * (float)cmask[b * LL + l];
                }
            }
            __syncthreads();
            if (tid < 32) {
                float v = sE[tid] + sE[tid + 32];
#pragma unroll
                for (int o = 16; o > 0; o >>= 1) v += __shfl_xor_sync(0xffffffffu, v, o);
                if (tid == 0) sSum[0] = v;
            }
            __syncthreads();
            if (tid < 64) sA[tid] = sE[tid] * __fdividef(1.0f, sSum[0]);
            __syncthreads();
            // gsum = a . ctxC  (2048 cols, coalesced)
            {
                u64 a00 = 0, a01 = 0, a10 = 0, a11 = 0;
                const float* base0 = g_ctxC + (size_t)b * LL * NCOL + tid * 4;
#pragma unroll 4
                for (int l = 0; l < LL; l++) {
                    float av = sA[l];
                    u64 ap = pk2(av, av);
                    const float* r = base0 + (size_t)l * NCOL;
                    float4 v0 = *(const float4*)r;
                    float4 v1 = *(const float4*)(r + 1024);
                    a00 = fma2(pk2(v0.x, v0.y), ap, a00);
                    a01 = fma2(pk2(v0.z, v0.w), ap, a01);
                    a10 = fma2(pk2(v1.x, v1.y), ap, a10);
                    a11 = fma2(pk2(v1.z, v1.w), ap, a11);
                }
                float2 r00 = upk2(a00), r01 = upk2(a01), r10 = upk2(a10), r11 = upk2(a11);
                *(float4*)&sG[tid * 4] = make_float4(r00.x, r00.y, r01.x, r01.y);
                *(float4*)&sG[1024 + tid * 4] = make_float4(r10.x, r10.y, r11.x, r11.y);
            }
            // out_x = a . context (512 cols)
            if (tid < 128) {
                u64 x0 = 0, x1 = 0;
                const float* cb = context + (size_t)b * LL * DD + tid * 4;
#pragma unroll 4
                for (int l = 0; l < LL; l++) {
                    float av = sA[l];
                    u64 ap = pk2(av, av);
                    float4 v = *(const float4*)(cb + (size_t)l * DD);
                    x0 = fma2(pk2(v.x, v.y), ap, x0);
                    x1 = fma2(pk2(v.z, v.w), ap, x1);
                }
                float2 r0 = upk2(x0), r1 = upk2(x1);
                *(float4*)(out_x + ((size_t)b * TT + t) * DD + tid * 4) =
                    make_float4(r0.x, r0.y, r1.x, r1.y);
            }
            __syncthreads();
            // fused LSTM epilogue: 2 channels per thread
            {
                int ch2 = tid * 2;
                const float* gbb = g_gbuf + (size_t)b * NCOL;
                float2 pi = *(const float2*)&gbb[ch2];
                float2 pf = *(const float2*)&gbb[512 + ch2];
                float2 pc = *(const float2*)&gbb[1024 + ch2];
                float2 po = *(const float2*)&gbb[1536 + ch2];
                float2 si = *(const float2*)&sG[ch2];
                float2 sf = *(const float2*)&sG[512 + ch2];
                float2 sc = *(const float2*)&sG[1024 + ch2];
                float2 so = *(const float2*)&sG[1536 + ch2];
                float2 cprev = make_float2(0.f, 0.f), hprev = make_float2(0.f, 0.f);
                if (t > 0) {
                    cprev = *(const float2*)&g_cst[(size_t)b * HH + ch2];
                    hprev = *(const float2*)&g_hp[(size_t)(ch2 >> 1) * 64 + b * 2];
                }
                float m = mask[b * TT + t];
                float hn[2], cn[2];
#pragma unroll
                for (int pp = 0; pp < 2; pp++) {
                    float ai = (pp ? pi.y + si.y : pi.x + si.x);
                    float af = (pp ? pf.y + sf.y : pf.x + sf.x);
                    float acv = (pp ? pc.y + sc.y : pc.x + sc.x);
                    float ao = (pp ? po.y + so.y : po.x + so.x);
                    float iv = sig_ap(ai);
                    float fv = sig_ap(af);
                    float gv = tanh_ap(acv);
                    float ov = sig_ap(ao);
                    float cp_ = pp ? cprev.y : cprev.x;
                    float hp_ = pp ? hprev.y : hprev.x;
                    float cnew = fv * cp_ + iv * gv;
                    float hnew = ov * tanh_ap(cnew);
                    hn[pp] = (1.f - m) * hp_ + m * hnew;
                    cn[pp] = (1.f - m) * cp_ + m * cnew;
                }
                *(float2*)(out_h + ((size_t)b * TT + t) * HH + ch2) = make_float2(hn[0], hn[1]);
                *(float2*)(out_c + ((size_t)b * TT + t) * HH + ch2) = make_float2(cn[0], cn[1]);
                *(float2*)&g_cst[(size_t)b * HH + ch2] = make_float2(cn[0], cn[1]);
                *(float2*)&g_hp[(size_t)(ch2 >> 1) * 64 + b * 2] = make_float2(hn[0], hn[1]);
            }
        }
        gbar(bid, tid, base + (unsigned)(2 * t + 2));
    }

    if (bid == 0 && tid == 0)
        *(volatile unsigned*)&g_epoch = base + (unsigned)(2 * TT);
}

// ---------------- host launcher ----------------
extern "C" void kernel_launch(void* const* d_in, const int* in_sizes, int n_in,
                              void* d_out, int out_size) {
    (void)in_sizes; (void)n_in; (void)out_size;
    const float* X    = (const float*)d_in[0];
    const float* ctx  = (const float*)d_in[1];
    const float* mask = (const float*)d_in[2];
    const int*   cm   = (const int*)d_in[3];
    const float* W[4]; const float* U[4]; const float* C[4]; const float* bi[4];
    for (int gg = 0; gg < 4; gg++) {
        W[gg]  = (const float*)d_in[4 + 4 * gg];
        U[gg]  = (const float*)d_in[5 + 4 * gg];
        C[gg]  = (const float*)d_in[6 + 4 * gg];
        bi[gg] = (const float*)d_in[7 + 4 * gg];
    }
    const float* attW1c = (const float*)d_in[20];
    const float* attW1h = (const float*)d_in[21];
    const float* attB1  = (const float*)d_in[22];
    const float* attW2  = (const float*)d_in[23];
    const float* attB2  = (const float*)d_in[24];
    float* out = (float*)d_out;

    float *xg_ptr = nullptr, *ctr_ptr = nullptr, *ctxC_ptr = nullptr, *zb_ptr = nullptr;
    cudaGetSymbolAddress((void**)&xg_ptr, g_xg);
    cudaGetSymbolAddress((void**)&ctr_ptr, g_ctr);
    cudaGetSymbolAddress((void**)&ctxC_ptr, g_ctxC);
    cudaGetSymbolAddress((void**)&zb_ptr, g_zbias);

    // xg = X@W + b : rows (t*32+b), cols 2048
    dim3 grid1(NCOL / 64, (TT * BB) / 64);
    gemm_proj<<<grid1, 256>>>(X, W[0], W[1], W[2], W[3],
                              bi[0], bi[1], bi[2], bi[3],
                              xg_ptr, NCOL, 512, 512, 1);
    // ctx_trans = context@att_ctx_W1 + b1 : rows (b*64+l), cols 256
    dim3 grid2(AA / 64, (BB * LL) / 64);
    gemm_proj<<<grid2, 256>>>(ctx, attW1c, attW1c, attW1c, attW1c,
                              attB1, attB1, attB1, attB1,
                              ctr_ptr, AA, AA, AA, 0);
    // ctxC = context@C_g : rows (b*64+l), cols 2048
    dim3 grid3(NCOL / 64, (BB * LL) / 64);
    gemm_proj<<<grid3, 256>>>(ctx, C[0], C[1], C[2], C[3],
                              zb_ptr, zb_ptr, zb_ptr, zb_ptr,
                              ctxC_ptr, NCOL, 512, 512, 0);
    // packed weights (U gates + att W1h)
    repack_wpk<<<(256 * UCOLS + 255) / 256, 256>>>(U[0], U[1], U[2], U[3], attW1h);

    size_t smem_bytes = (size_t)SMEM_FLOATS * sizeof(float);
    static bool attr_set = false;
    if (!attr_set) {
        cudaFuncSetAttribute(recur_kernel, cudaFuncAttributeMaxDynamicSharedMemorySize,
                             (int)smem_bytes);
        attr_set = true;
    }
    recur_kernel<<<NBLK, 256, smem_bytes>>>(ctx, mask, cm, attW2, attB2, out);
}

// round 6
// speedup vs baseline: 3.7036x; 1.3558x over previous
#include <cuda_runtime.h>
#include <cstdint>
#include <cstddef>

#define BB 32
#define TT 128
#define LL 64
#define HH 512
#define AA 256
#define DD 512
#define NCOL 2048
#define UCOLS 2304          // 2048 gate cols + 256 att cols
#define NBLK 144            // P1: 2304/16 cols; P2: first 128 = 32 b x 4 quarters
#define WSTRIDE (UCOLS * 2)
#define QCH 128             // channels per quarter

typedef unsigned long long u64;

// ---------------- device scratch ----------------
__device__ float g_xg[(size_t)TT * BB * NCOL];     // [t*32+b][col]
__device__ float g_ctr[(size_t)BB * LL * AA];      // ctx_trans [b*64+l][a]
__device__ float g_ctxC[(size_t)BB * LL * NCOL];   // context@C [b*64+l][col]
__device__ float g_Wpk[(size_t)256 * UCOLS * 2];   // [k2][c]{keven,kodd}
__device__ float g_gbuf[(size_t)BB * NCOL];        // [b][col] xg + h@U
__device__ float g_attv[(size_t)BB * AA];          // [b][a] h@W1h
__device__ float g_hp[(size_t)256 * BB * 2];       // h pairs [k2][b]{e,o}
__device__ float g_cst[(size_t)BB * HH];           // c state [b][ch]
__device__ float g_zbias[512];
__device__ unsigned g_arr[NBLK * 32];              // padded arrival flags (128B apart)
__device__ unsigned g_rel;
__device__ unsigned g_epoch;

// ---------------- helpers ----------------
__device__ __forceinline__ u64 pk2(float lo, float hi) {
    u64 r; asm("mov.b64 %0, {%1,%2};" : "=l"(r) : "f"(lo), "f"(hi)); return r;
}
__device__ __forceinline__ float2 upk2(u64 v) {
    float2 r; asm("mov.b64 {%0,%1}, %2;" : "=f"(r.x), "=f"(r.y) : "l"(v)); return r;
}
__device__ __forceinline__ u64 fma2(u64 a, u64 b, u64 c) {
    u64 d; asm("fma.rn.f32x2 %0, %1, %2, %3;" : "=l"(d) : "l"(a), "l"(b), "l"(c)); return d;
}
__device__ __forceinline__ float tanh_ap(float x) {
    float y; asm("tanh.approx.f32 %0, %1;" : "=f"(y) : "f"(x)); return y;
}
__device__ __forceinline__ float sig_ap(float x) {
    return fmaf(tanh_ap(0.5f * x), 0.5f, 0.5f);
}

__device__ __forceinline__ void gbar(int bid, int tid, unsigned gen) {
    __syncthreads();
    if (tid == 0) {
        __threadfence();
        *(volatile unsigned*)&g_arr[bid * 32] = gen;
    }
    if (bid == 0) {
        if (tid < NBLK) {
            while (*(volatile unsigned*)&g_arr[tid * 32] < gen) { }
        }
        __syncthreads();
        if (tid == 0) {
            __threadfence();
            *(volatile unsigned*)&g_rel = gen;
        }
    }
    if (tid == 0) {
        while (*(volatile unsigned*)&g_rel < gen) { }
        __threadfence();
    }
    __syncthreads();
}

// ---------------- prologue GEMM ----------------
__global__ void __launch_bounds__(256) gemm_proj(
    const float* __restrict__ A,
    const float* __restrict__ Wa, const float* __restrict__ Wb,
    const float* __restrict__ Wc, const float* __restrict__ Wd,
    const float* __restrict__ ba, const float* __restrict__ bbi,
    const float* __restrict__ bc, const float* __restrict__ bd,
    float* __restrict__ Out, int Ncols, int wN, int wstride, int tb_mode)
{
    __shared__ float As[16][64];
    __shared__ float Bs[16][64];
    int tid = threadIdx.x;
    int ntile = blockIdx.x, mtile = blockIdx.y;

    int gate = (ntile * 64) / 512;
    const float* Wsel = (gate == 0) ? Wa : (gate == 1) ? Wb : (gate == 2) ? Wc : Wd;
    const float* bsel = (gate == 0) ? ba : (gate == 1) ? bbi : (gate == 2) ? bc : bd;
    int ncolbase = (ntile * 64) % wN;

    int a_r = tid >> 2;
    int a_k = (tid & 3) * 4;
    int grow = mtile * 64 + a_r;
    const float* aptr;
    if (tb_mode) {
        int t = grow >> 5, b = grow & 31;
        aptr = A + ((size_t)(b * TT + t)) * DD;
    } else {
        aptr = A + (size_t)grow * DD;
    }
    int b_k = tid >> 4;
    int b_n = (tid & 15) * 4;

    int tx = tid & 15, ty = tid >> 4;
    float acc[4][4];
#pragma unroll
    for (int i = 0; i < 4; i++)
#pragma unroll
        for (int j = 0; j < 4; j++) acc[i][j] = 0.f;

    for (int k0 = 0; k0 < DD; k0 += 16) {
        float4 av = *(const float4*)(aptr + k0 + a_k);
        float4 bv = *(const float4*)(Wsel + (size_t)(k0 + b_k) * wstride + ncolbase + b_n);
        __syncthreads();
        As[a_k + 0][a_r] = av.x; As[a_k + 1][a_r] = av.y;
        As[a_k + 2][a_r] = av.z; As[a_k + 3][a_r] = av.w;
        *(float4*)&Bs[b_k][b_n] = bv;
        __syncthreads();
#pragma unroll
        for (int kk = 0; kk < 16; kk++) {
            float4 a4 = *(float4*)&As[kk][ty * 4];
            float4 b4 = *(float4*)&Bs[kk][tx * 4];
            float aa[4] = {a4.x, a4.y, a4.z, a4.w};
            float bb4[4] = {b4.x, b4.y, b4.z, b4.w};
#pragma unroll
            for (int i = 0; i < 4; i++)
#pragma unroll
                for (int j = 0; j < 4; j++) acc[i][j] += aa[i] * bb4[j];
        }
    }
#pragma unroll
    for (int i = 0; i < 4; i++) {
        int gr = mtile * 64 + ty * 4 + i;
        float4 v;
        v.x = acc[i][0] + bsel[(ncolbase + tx * 4 + 0) % wN];
        v.y = acc[i][1] + bsel[(ncolbase + tx * 4 + 1) % wN];
        v.z = acc[i][2] + bsel[(ncolbase + tx * 4 + 2) % wN];
        v.w = acc[i][3] + bsel[(ncolbase + tx * 4 + 3) % wN];
        *(float4*)(Out + (size_t)gr * Ncols + ntile * 64 + tx * 4) = v;
    }
}

// ---------------- unified weight repack ----------------
__global__ void __launch_bounds__(256) repack_wpk(
    const float* __restrict__ U0, const float* __restrict__ U1,
    const float* __restrict__ U2, const float* __restrict__ U3,
    const float* __restrict__ W1h)
{
    int i = blockIdx.x * 256 + threadIdx.x;
    if (i >= 256 * UCOLS) return;
    int k2 = i / UCOLS;
    int c = i - k2 * UCOLS;
    float e, o;
    if (c < 2048) {
        int g = c >> 9, ch = c & 511;
        const float* Ug = (g == 0) ? U0 : (g == 1) ? U1 : (g == 2) ? U2 : U3;
        e = Ug[(size_t)(2 * k2) * 512 + ch];
        o = Ug[(size_t)(2 * k2 + 1) * 512 + ch];
    } else {
        int a = c - 2048;
        e = W1h[(size_t)(2 * k2) * AA + a];
        o = W1h[(size_t)(2 * k2 + 1) * AA + a];
    }
    g_Wpk[(size_t)i * 2 + 0] = e;
    g_Wpk[(size_t)i * 2 + 1] = o;
}

// dynamic smem: sCtxC[32768] | sTp[16384] | sRed[2048] | sAux[768]  = 51968 floats (203KB)
#define SMEM_FLOATS (32768 + 16384 + 2048 + 768)

// ---------------- persistent recurrent kernel ----------------
__global__ void __launch_bounds__(256, 1) recur_kernel(
    const float* __restrict__ context,
    const float* __restrict__ mask,
    const int*   __restrict__ cmask,
    const float* __restrict__ W2, const float* __restrict__ b2,
    float* __restrict__ out)
{
    extern __shared__ float smem[];
    float* sCtxC = smem;                       // [l*4+g][128] persistent slice
    float* sTp   = smem + 32768;               // P1 h pairs [k2][64]
    float* sRed  = smem + 32768 + 16384;       // 2048 scratch
    float* sAux  = smem + 32768 + 16384 + 2048;
    float* sAtt  = sAux;                       // 256
    float* sW2s  = sAux + 256;                 // 256
    float* sE    = sAux + 512;                 // 64
    float* sA    = sAux + 576;                 // 64
    float* sSum  = sAux + 640;                 // 1

    const int tid = threadIdx.x;
    const int bid = blockIdx.x;
    float* out_h = out;
    float* out_c = out + (size_t)BB * TT * HH;
    float* out_x = out + (size_t)2 * BB * TT * HH;
    const float b2v = b2[0];

    unsigned base = *(volatile unsigned*)&g_epoch;

    // P1 roles
    const int c0 = bid * 16;
    const int cp = tid & 7;
    const int bq = (tid >> 3) & 7;
    const int kq = tid >> 6;
    const int c  = c0 + cp * 2;

    // P2 roles
    const bool p2act = (bid < 128);
    const int pb = bid >> 2;        // batch
    const int pq = bid & 3;         // quarter

    // ---- one-time: load persistent ctxC slice + W2 ----
    if (p2act) {
        for (int idx4 = tid; idx4 < 8192; idx4 += 256) {
            int l = idx4 >> 7;
            int r = idx4 & 127;
            int g = r >> 5, i4 = r & 31;
            float4 v = *(const float4*)(g_ctxC + ((size_t)(pb * 64 + l)) * NCOL +
                                        g * 512 + pq * QCH + i4 * 4);
            *(float4*)&sCtxC[(size_t)(l * 4 + g) * 128 + i4 * 4] = v;
        }
        sW2s[tid] = W2[tid];
    }

    for (int t = 0; t < TT; t++) {
        // ================= PHASE 1: unified GEMM over h =================
        if (t > 0) {
            const float4* src = (const float4*)g_hp;
            for (int f4 = tid; f4 < 4096; f4 += 256)
                *(float4*)&sTp[f4 * 4] = src[f4];
        }
        __syncthreads();

        u64 ac[2][4];
#pragma unroll
        for (int i = 0; i < 2; i++)
#pragma unroll
            for (int j = 0; j < 4; j++) ac[i][j] = 0;
        if (t > 0) {
            const float* wp = g_Wpk + ((size_t)(kq * 64) * UCOLS + c) * 2;
            const float* hp = sTp + (kq * 64) * 64 + bq * 8;
#pragma unroll 8
            for (int p = 0; p < 64; p++) {
                float4 wv  = *(const float4*)wp;
                float4 h01 = *(const float4*)hp;
                float4 h23 = *(const float4*)(hp + 4);
                u64 w0 = pk2(wv.x, wv.y);
                u64 w1 = pk2(wv.z, wv.w);
                u64 hb0 = pk2(h01.x, h01.y);
                u64 hb1 = pk2(h01.z, h01.w);
                u64 hb2 = pk2(h23.x, h23.y);
                u64 hb3 = pk2(h23.z, h23.w);
                ac[0][0] = fma2(w0, hb0, ac[0][0]);
                ac[0][1] = fma2(w0, hb1, ac[0][1]);
                ac[0][2] = fma2(w0, hb2, ac[0][2]);
                ac[0][3] = fma2(w0, hb3, ac[0][3]);
                ac[1][0] = fma2(w1, hb0, ac[1][0]);
                ac[1][1] = fma2(w1, hb1, ac[1][1]);
                ac[1][2] = fma2(w1, hb2, ac[1][2]);
                ac[1][3] = fma2(w1, hb3, ac[1][3]);
                wp += WSTRIDE; hp += 64;
            }
        }
#pragma unroll
        for (int bi = 0; bi < 4; bi++) {
            float2 r0 = upk2(ac[0][bi]);
            float2 r1 = upk2(ac[1][bi]);
            *(float2*)&sRed[kq * 512 + (bq * 4 + bi) * 16 + cp * 2] =
                make_float2(r0.x + r0.y, r1.x + r1.y);
        }
        __syncthreads();
#pragma unroll
        for (int o = tid; o < 512; o += 256) {
            float s = sRed[o] + sRed[512 + o] + sRed[1024 + o] + sRed[1536 + o];
            int b = o >> 4, colL = o & 15;
            if (bid < 128) {
                int col = c0 + colL;
                s += g_xg[((size_t)t * BB + b) * NCOL + col];
                g_gbuf[(size_t)b * NCOL + col] = s;
            } else {
                g_attv[b * AA + (c0 - 2048) + colL] = s;
            }
        }
        gbar(bid, tid, base + (unsigned)(2 * t + 1));

        // ================= PHASE 2: per (b, quarter) block =================
        if (p2act) {
            const int b = pb;
            sAtt[tid] = g_attv[b * AA + tid];
            __syncthreads();
            // scores (warp per l, 8 l per warp)
            {
                int warp = tid >> 5, lane = tid & 31;
#pragma unroll
                for (int i = 0; i < 8; i++) {
                    int l = warp * 8 + i;
                    const float* ct = g_ctr + ((size_t)b * LL + l) * AA;
                    float p = 0.f;
#pragma unroll
                    for (int j = 0; j < 8; j++) {
                        int a = lane + j * 32;
                        p += tanh_ap(ct[a] + sAtt[a]) * sW2s[a];
                    }
#pragma unroll
                    for (int o = 16; o > 0; o >>= 1) p += __shfl_xor_sync(0xffffffffu, p, o);
                    if (lane == 0)
                        sE[l] = __expf(p + b2v) * (float)cmask[b * LL + l];
                }
            }
            __syncthreads();
            if (tid < 32) {
                float v = sE[tid] + sE[tid + 32];
#pragma unroll
                for (int o = 16; o > 0; o >>= 1) v += __shfl_xor_sync(0xffffffffu, v, o);
                if (tid == 0) sSum[0] = v;
            }
            __syncthreads();
            if (tid < 64) sA[tid] = sE[tid] * __fdividef(1.0f, sSum[0]);
            __syncthreads();

            // out_x: 128 dims (quarter), split (lh 0..7) x (d4 0..31)
            {
                int lh = tid >> 5, d4 = tid & 31;
                float4 xp = make_float4(0.f, 0.f, 0.f, 0.f);
                const float* cb = context + ((size_t)b * LL + lh * 8) * DD + pq * QCH + d4 * 4;
#pragma unroll
                for (int li = 0; li < 8; li++) {
                    float av = sA[lh * 8 + li];
                    float4 v = *(const float4*)(cb + (size_t)li * DD);
                    xp.x += av * v.x; xp.y += av * v.y; xp.z += av * v.z; xp.w += av * v.w;
                }
                *(float4*)&sRed[tid * 4] = xp;
            }
            __syncthreads();
            if (tid < 32) {
                float4 s = make_float4(0.f, 0.f, 0.f, 0.f);
#pragma unroll
                for (int lh = 0; lh < 8; lh++) {
                    float4 v = *(const float4*)&sRed[(lh * 32 + tid) * 4];
                    s.x += v.x; s.y += v.y; s.z += v.z; s.w += v.w;
                }
                *(float4*)(out_x + ((size_t)b * TT + t) * DD + pq * QCH + tid * 4) = s;
            }
            __syncthreads();

            // gsum from SMEM ctxC: (lq 0..3) x (i2 0..63), 2 ch per thread
            {
                int lq = tid >> 6, i2 = tid & 63;
                u64 acg[4] = {0, 0, 0, 0};
                const float* sl = sCtxC + (size_t)(lq * 16) * 512 + i2 * 2;
#pragma unroll 4
                for (int li = 0; li < 16; li++) {
                    float av = sA[lq * 16 + li];
                    u64 ap = pk2(av, av);
#pragma unroll
                    for (int g = 0; g < 4; g++) {
                        float2 v = *(const float2*)(sl + g * 128);
                        acg[g] = fma2(pk2(v.x, v.y), ap, acg[g]);
                    }
                    sl += 512;
                }
#pragma unroll
                for (int g = 0; g < 4; g++) {
                    float2 r = upk2(acg[g]);
                    *(float2*)&sRed[((lq * 4 + g) * 64 + i2) * 2] = r;
                }
            }
            __syncthreads();

            // final reduce + fused LSTM epilogue: thread i2 < 64 handles ch pair
            if (tid < 64) {
                int i2 = tid;
                int ch0 = pq * QCH + i2 * 2;
                float gs[4][2];
#pragma unroll
                for (int g = 0; g < 4; g++) {
                    float s0 = 0.f, s1 = 0.f;
#pragma unroll
                    for (int lq = 0; lq < 4; lq++) {
                        float2 v = *(const float2*)&sRed[((lq * 4 + g) * 64 + i2) * 2];
                        s0 += v.x; s1 += v.y;
                    }
                    float2 gb = *(const float2*)&g_gbuf[(size_t)b * NCOL + g * 512 + ch0];
                    gs[g][0] = s0 + gb.x;
                    gs[g][1] = s1 + gb.y;
                }
                float2 cprev = make_float2(0.f, 0.f), hprev = make_float2(0.f, 0.f);
                if (t > 0) {
                    cprev = *(const float2*)&g_cst[(size_t)b * HH + ch0];
                    hprev = *(const float2*)&g_hp[(size_t)(ch0 >> 1) * 64 + b * 2];
                }
                float m = mask[b * TT + t];
                float hn[2], cn[2];
#pragma unroll
                for (int pp = 0; pp < 2; pp++) {
                    float iv = sig_ap(gs[0][pp]);
                    float fv = sig_ap(gs[1][pp]);
                    float gv = tanh_ap(gs[2][pp]);
                    float ov = sig_ap(gs[3][pp]);
                    float cp_ = pp ? cprev.y : cprev.x;
                    float hp_ = pp ? hprev.y : hprev.x;
                    float cnew = fv * cp_ + iv * gv;
                    float hnew = ov * tanh_ap(cnew);
                    hn[pp] = (1.f - m) * hp_ + m * hnew;
                    cn[pp] = (1.f - m) * cp_ + m * cnew;
                }
                *(float2*)(out_h + ((size_t)b * TT + t) * HH + ch0) = make_float2(hn[0], hn[1]);
                *(float2*)(out_c + ((size_t)b * TT + t) * HH + ch0) = make_float2(cn[0], cn[1]);
                *(float2*)&g_cst[(size_t)b * HH + ch0] = make_float2(cn[0], cn[1]);
                *(float2*)&g_hp[(size_t)(ch0 >> 1) * 64 + b * 2] = make_float2(hn[0], hn[1]);
            }
        }
        gbar(bid, tid, base + (unsigned)(2 * t + 2));
    }

    if (bid == 0 && tid == 0)
        *(volatile unsigned*)&g_epoch = base + (unsigned)(2 * TT);
}

// ---------------- host launcher ----------------
extern "C" void kernel_launch(void* const* d_in, const int* in_sizes, int n_in,
                              void* d_out, int out_size) {
    (void)in_sizes; (void)n_in; (void)out_size;
    const float* X    = (const float*)d_in[0];
    const float* ctx  = (const float*)d_in[1];
    const float* mask = (const float*)d_in[2];
    const int*   cm   = (const int*)d_in[3];
    const float* W[4]; const float* U[4]; const float* C[4]; const float* bi[4];
    for (int gg = 0; gg < 4; gg++) {
        W[gg]  = (const float*)d_in[4 + 4 * gg];
        U[gg]  = (const float*)d_in[5 + 4 * gg];
        C[gg]  = (const float*)d_in[6 + 4 * gg];
        bi[gg] = (const float*)d_in[7 + 4 * gg];
    }
    const float* attW1c = (const float*)d_in[20];
    const float* attW1h = (const float*)d_in[21];
    const float* attB1  = (const float*)d_in[22];
    const float* attW2  = (const float*)d_in[23];
    const float* attB2  = (const float*)d_in[24];
    float* out = (float*)d_out;

    float *xg_ptr = nullptr, *ctr_ptr = nullptr, *ctxC_ptr = nullptr, *zb_ptr = nullptr;
    cudaGetSymbolAddress((void**)&xg_ptr, g_xg);
    cudaGetSymbolAddress((void**)&ctr_ptr, g_ctr);
    cudaGetSymbolAddress((void**)&ctxC_ptr, g_ctxC);
    cudaGetSymbolAddress((void**)&zb_ptr, g_zbias);

    dim3 grid1(NCOL / 64, (TT * BB) / 64);
    gemm_proj<<<grid1, 256>>>(X, W[0], W[1], W[2], W[3],
                              bi[0], bi[1], bi[2], bi[3],
                              xg_ptr, NCOL, 512, 512, 1);
    dim3 grid2(AA / 64, (BB * LL) / 64);
    gemm_proj<<<grid2, 256>>>(ctx, attW1c, attW1c, attW1c, attW1c,
                              attB1, attB1, attB1, attB1,
                              ctr_ptr, AA, AA, AA, 0);
    dim3 grid3(NCOL / 64, (BB * LL) / 64);
    gemm_proj<<<grid3, 256>>>(ctx, C[0], C[1], C[2], C[3],
                              zb_ptr, zb_ptr, zb_ptr, zb_ptr,
                              ctxC_ptr, NCOL, 512, 512, 0);
    repack_wpk<<<(256 * UCOLS + 255) / 256, 256>>>(U[0], U[1], U[2], U[3], attW1h);

    size_t smem_bytes = (size_t)SMEM_FLOATS * sizeof(float);
    static bool attr_set = false;
    if (!attr_set) {
        cudaFuncSetAttribute(recur_kernel, cudaFuncAttributeMaxDynamicSharedMemorySize,
                             (int)smem_bytes);
        attr_set = true;
    }
    recur_kernel<<<NBLK, 256, smem_bytes>>>(ctx, mask, cm, attW2, attB2, out);
}